// round 3
// baseline (speedup 1.0000x reference)
#include <cuda_runtime.h>
#include <math.h>

#define E 512
#define T 1024
#define BB 8
#define HN 8
#define DH 64
#define HALF 32
#define NL 4
#define X 8
#define TOPK 2
#define CAP 2048
#define H4 2048
#define NTOK 8192
#define HIGH 32000
#define HID 1024

// ---------------- scratch (device globals; no allocation allowed) ----------------
__device__ float g_x[NTOK * E];
__device__ float g_h[NTOK * E];
__device__ float g_qkv[NTOK * 3 * E];
__device__ float g_att[NTOK * E];
__device__ int   g_topi[NTOK * TOPK];
__device__ float g_gatev[NTOK * TOPK];
__device__ int   g_idx[X * CAP];
__device__ float g_gate[X * CAP];
__device__ int   g_slot[NTOK * TOPK];
__device__ int   g_cnt[X];
__device__ float g_ein[X * CAP * E];
__device__ float g_ehid[(long)X * CAP * H4];
__device__ float g_eout[X * CAP * E];
__device__ float g_pool[BB * E];
__device__ float g_hv[BB * HIGH];
__device__ float g_o1[BB * HID];

// ---------------- embed ----------------
__global__ void embed_kernel(const float* __restrict__ tok, const float* __restrict__ pos,
                             const int* __restrict__ ids) {
    int n = blockIdx.x;
    int t = n % T;
    int id = ids[n];
    const float4* te = (const float4*)(tok + (long)id * E);
    const float4* pe = (const float4*)(pos + (long)t * E);
    float4* xr = (float4*)(g_x + (long)n * E);
    int i = threadIdx.x;  // 128 threads, E/4 = 128
    float4 a = te[i], b = pe[i];
    a.x += b.x; a.y += b.y; a.z += b.z; a.w += b.w;
    xr[i] = a;
}

// ---------------- layernorm (row per block, 256 threads) ----------------
__global__ void ln_kernel(const float* __restrict__ in, const float* __restrict__ w,
                          const float* __restrict__ b, float* __restrict__ out) {
    int n = blockIdx.x;
    int tid = threadIdx.x, lane = tid & 31, wid = tid >> 5;
    __shared__ float red[8];
    const float* r = in + (long)n * E;
    float v0 = r[tid], v1 = r[tid + 256];
    float s = v0 + v1;
    #pragma unroll
    for (int o = 16; o; o >>= 1) s += __shfl_xor_sync(~0u, s, o);
    if (lane == 0) red[wid] = s;
    __syncthreads();
    float tot = 0;
    #pragma unroll
    for (int w8 = 0; w8 < 8; w8++) tot += red[w8];
    float mean = tot * (1.0f / E);
    float d0 = v0 - mean, d1 = v1 - mean;
    float sq = d0 * d0 + d1 * d1;
    __syncthreads();
    #pragma unroll
    for (int o = 16; o; o >>= 1) sq += __shfl_xor_sync(~0u, sq, o);
    if (lane == 0) red[wid] = sq;
    __syncthreads();
    float tv = 0;
    #pragma unroll
    for (int w8 = 0; w8 < 8; w8++) tv += red[w8];
    float inv = rsqrtf(tv * (1.0f / E) + 1e-5f);
    out[(long)n * E + tid] = d0 * inv * w[tid] + b[tid];
    out[(long)n * E + tid + 256] = d1 * inv * w[tid + 256] + b[tid + 256];
}

// ---------------- generic tiled GEMM: C = act(A @ W^T + bias [+resid]) ----------------
__global__ void __launch_bounds__(256, 2)
gemm_kernel(const float* __restrict__ A, const float* __restrict__ W,
            const float* __restrict__ bias, const float* __restrict__ resid,
            float* __restrict__ C, int M, int N, int Kd,
            int aB, int wB, int bB, int cB, int act) {
    int z = blockIdx.z;
    A += (long)z * aB;
    W += (long)z * wB;
    C += (long)z * cB;
    __shared__ float As[8][128];
    __shared__ float Ws[8][128];
    int tid = threadIdx.x;
    int tx = tid & 15, ty = tid >> 4;
    int m0 = blockIdx.y * 128, n0 = blockIdx.x * 128;
    float acc[8][8] = {};
    int lrow = tid >> 1, lk = (tid & 1) * 4;
    for (int k0 = 0; k0 < Kd; k0 += 8) {
        float4 va = *(const float4*)(A + (long)(m0 + lrow) * Kd + k0 + lk);
        float4 vw = *(const float4*)(W + (long)(n0 + lrow) * Kd + k0 + lk);
        As[lk + 0][lrow] = va.x; As[lk + 1][lrow] = va.y;
        As[lk + 2][lrow] = va.z; As[lk + 3][lrow] = va.w;
        Ws[lk + 0][lrow] = vw.x; Ws[lk + 1][lrow] = vw.y;
        Ws[lk + 2][lrow] = vw.z; Ws[lk + 3][lrow] = vw.w;
        __syncthreads();
        #pragma unroll
        for (int kk = 0; kk < 8; kk++) {
            float a[8], w8[8];
            #pragma unroll
            for (int i = 0; i < 8; i++) a[i] = As[kk][ty * 8 + i];
            #pragma unroll
            for (int j = 0; j < 8; j++) w8[j] = Ws[kk][tx * 8 + j];
            #pragma unroll
            for (int i = 0; i < 8; i++)
                #pragma unroll
                for (int j = 0; j < 8; j++) acc[i][j] += a[i] * w8[j];
        }
        __syncthreads();
    }
    #pragma unroll
    for (int i = 0; i < 8; i++) {
        int m = m0 + ty * 8 + i;
        #pragma unroll
        for (int j = 0; j < 8; j++) {
            int n = n0 + tx * 8 + j;
            float v = acc[i][j];
            if (bias) v += bias[(long)z * bB + n];
            if (resid) v += resid[(long)m * N + n];
            if (act) v = fmaxf(v, 0.0f);
            C[(long)m * N + n] = v;
        }
    }
}

// ---------------- RoPE in-place on q,k of g_qkv ----------------
__global__ void rope_kernel() {
    int n = blockIdx.x;
    int tid = threadIdx.x;  // 512
    int which = tid >> 8;   // 0=q, 1=k
    int rem = tid & 255;
    int h = rem >> 5, j = rem & 31;
    int t = n % T;
    float div = expf(-(float)j * (9.210340371976184f / 32.0f));
    float ang = (float)t * div;
    float c = cosf(ang), s = sinf(ang);
    float* p = g_qkv + (long)n * 3 * E + which * E + h * DH;
    float a1 = p[j], a2 = p[j + HALF];
    p[j] = a1 * c - a2 * s;
    p[j + HALF] = a2 * c + a1 * s;
}

// ---------------- attention: one warp per (b,h,t), online softmax ----------------
// NOTE: the reference does einsum(...->bthd) then transpose(0,2,1,3).reshape(b,t,E),
// which scrambles (h,t,d) -> row t' = h*128 + t/8, channel e' = (t%8)*64 + d.
// We write the output directly in that permuted layout.
__global__ void attn_kernel() {
    int gw = (blockIdx.x * blockDim.x + threadIdx.x) >> 5;
    int lane = threadIdx.x & 31;
    int b = gw >> 13;
    int rem = gw & 8191;
    int h = rem >> 10;
    int t = rem & 1023;
    int n = b * T + t;
    const float* qr = g_qkv + (long)n * 3 * E + h * DH;
    float q0 = qr[lane] * 0.125f, q1 = qr[lane + 32] * 0.125f;
    float m = -INFINITY, lsum = 0.0f, a0 = 0.0f, a1 = 0.0f;
    const float* kbase = g_qkv + (long)b * T * 3 * E + E + h * DH;
    for (int s = 0; s < T; s++) {
        const float* kr = kbase + (long)s * 3 * E;
        float p = q0 * kr[lane] + q1 * kr[lane + 32];
        #pragma unroll
        for (int o = 16; o; o >>= 1) p += __shfl_xor_sync(~0u, p, o);
        float mn = fmaxf(m, p);
        float corr = expf(m - mn);
        float w = expf(p - mn);
        lsum = lsum * corr + w;
        const float* vr = kr + E;
        a0 = a0 * corr + w * vr[lane];
        a1 = a1 * corr + w * vr[lane + 32];
        m = mn;
    }
    float inv = 1.0f / lsum;
    // permuted output layout (matches reference's transpose+reshape)
    int tp = h * 128 + (t >> 3);
    int ep = (t & 7) * 64;
    float* orow = g_att + ((long)b * T + tp) * E + ep;
    orow[lane] = a0 * inv;
    orow[lane + 32] = a1 * inv;
}

// ---------------- router: warp per token, top-2 + gates ----------------
__global__ void router_kernel(const float* __restrict__ rw, const float* __restrict__ rb,
                              const float* __restrict__ nw, const float* __restrict__ nb,
                              const float* __restrict__ rn) {
    int gw = (blockIdx.x * blockDim.x + threadIdx.x) >> 5;
    int lane = threadIdx.x & 31;
    if (gw >= NTOK) return;
    const float* h = g_h + (long)gw * E;
    float hr[16];
    #pragma unroll
    for (int j = 0; j < 16; j++) hr[j] = h[lane + 32 * j];
    float lg[X], ng[X];
    #pragma unroll
    for (int e = 0; e < X; e++) {
        float a = 0, bn = 0;
        const float* wr = rw + (long)e * E;
        const float* wn = nw + (long)e * E;
        #pragma unroll
        for (int j = 0; j < 16; j++) {
            a += hr[j] * wr[lane + 32 * j];
            bn += hr[j] * wn[lane + 32 * j];
        }
        #pragma unroll
        for (int o = 16; o; o >>= 1) {
            a += __shfl_xor_sync(~0u, a, o);
            bn += __shfl_xor_sync(~0u, bn, o);
        }
        lg[e] = a;
        ng[e] = bn;
    }
    if (lane == 0) {
        float noisy[X];
        #pragma unroll
        for (int e = 0; e < X; e++) {
            float lo = lg[e] + rb[e];
            float nl = ng[e] + nb[e];
            float sp = nl > 0.0f ? nl + log1pf(expf(-nl)) : log1pf(expf(nl));
            noisy[e] = lo + rn[(long)gw * X + e] * sp;
        }
        int b1 = 0; float v1 = noisy[0];
        #pragma unroll
        for (int e = 1; e < X; e++) if (noisy[e] > v1) { v1 = noisy[e]; b1 = e; }
        int b2 = -1; float v2 = -INFINITY;
        #pragma unroll
        for (int e = 0; e < X; e++) if (e != b1 && noisy[e] > v2) { v2 = noisy[e]; b2 = e; }
        float zz = expf(v2 - v1);
        float p1 = 1.0f / (1.0f + zz);
        float p2 = zz / (1.0f + zz);
        g_topi[gw * 2] = b1; g_topi[gw * 2 + 1] = b2;
        g_gatev[gw * 2] = p1; g_gatev[gw * 2 + 1] = p2;
    }
}

// ---------------- dispatch: ordered compaction per expert (token order preserved) ----------------
__global__ void dispatch_kernel() {
    int e = blockIdx.x;
    int tid = threadIdx.x, lane = tid & 31, wid = tid >> 5;
    __shared__ int wsum[8];
    __shared__ int sbase;
    if (tid == 0) sbase = 0;
    __syncthreads();
    for (int c = 0; c < NTOK; c += 256) {
        int n = c + tid;
        int k = -1;
        if (g_topi[n * 2] == e) k = 0;
        else if (g_topi[n * 2 + 1] == e) k = 1;
        unsigned bal = __ballot_sync(~0u, k >= 0);
        if (lane == 0) wsum[wid] = __popc(bal);
        __syncthreads();
        int pre = 0, total = 0;
        #pragma unroll
        for (int w8 = 0; w8 < 8; w8++) {
            total += wsum[w8];
            if (w8 < wid) pre += wsum[w8];
        }
        if (k >= 0) {
            int pos = sbase + pre + __popc(bal & ((1u << lane) - 1));
            if (pos < CAP) {
                g_idx[e * CAP + pos] = n;
                g_gate[e * CAP + pos] = g_gatev[n * 2 + k];
                g_slot[n * 2 + k] = e * CAP + pos;
            } else {
                g_slot[n * 2 + k] = -1;
            }
        }
        __syncthreads();
        if (tid == 0) sbase += total;
        __syncthreads();
    }
    if (tid == 0) g_cnt[e] = sbase < CAP ? sbase : CAP;
}

// ---------------- gather expert inputs (zero-fill beyond count) ----------------
__global__ void gather_kernel() {
    int r = blockIdx.x;  // X*CAP rows
    int e = r / CAP, s = r % CAP;
    float4* dst = (float4*)(g_ein + (long)r * E);
    int i = threadIdx.x;  // 128 => one float4 each
    if (s < g_cnt[e]) {
        const float4* src = (const float4*)(g_h + (long)g_idx[r] * E);
        dst[i] = src[i];
    } else {
        float4 zf = {0, 0, 0, 0};
        dst[i] = zf;
    }
}

// ---------------- combine: x += sum_k gate * expert_out (deterministic, per token) ----------------
__global__ void combine_kernel() {
    int n = blockIdx.x;
    int i = threadIdx.x;  // 128 float4s
    float4* xr = (float4*)(g_x + (long)n * E);
    float4 v = xr[i];
    #pragma unroll
    for (int k = 0; k < 2; k++) {
        int s = g_slot[n * 2 + k];
        if (s >= 0) {
            float g = g_gate[s];
            float4 eo = ((const float4*)(g_eout + (long)s * E))[i];
            v.x += g * eo.x; v.y += g * eo.y; v.z += g * eo.z; v.w += g * eo.w;
        }
    }
    xr[i] = v;
}

// ---------------- attention pooling (block per batch) ----------------
__global__ void pool_kernel(const float* __restrict__ pq) {
    int b = blockIdx.x;
    int tid = threadIdx.x, lane = tid & 31, wid = tid >> 5;
    __shared__ float s[T];
    __shared__ float red[8];
    const float* hb = g_h + (long)b * T * E;
    for (int t = wid; t < T; t += 8) {
        float acc = 0;
        const float* row = hb + (long)t * E;
        for (int i = lane; i < E; i += 32) acc += pq[i] * row[i];
        #pragma unroll
        for (int o = 16; o; o >>= 1) acc += __shfl_xor_sync(~0u, acc, o);
        if (lane == 0) s[t] = acc * (1.0f / 22.627416997969522f);
    }
    __syncthreads();
    float m = -INFINITY;
    for (int t = tid; t < T; t += 256) m = fmaxf(m, s[t]);
    #pragma unroll
    for (int o = 16; o; o >>= 1) m = fmaxf(m, __shfl_xor_sync(~0u, m, o));
    if (lane == 0) red[wid] = m;
    __syncthreads();
    float mm = red[0];
    #pragma unroll
    for (int w8 = 1; w8 < 8; w8++) mm = fmaxf(mm, red[w8]);
    float sum = 0;
    for (int t = tid; t < T; t += 256) {
        float e2 = expf(s[t] - mm);
        s[t] = e2;
        sum += e2;
    }
    #pragma unroll
    for (int o = 16; o; o >>= 1) sum += __shfl_xor_sync(~0u, sum, o);
    __syncthreads();
    if (lane == 0) red[wid] = sum;
    __syncthreads();
    float tot = 0;
    #pragma unroll
    for (int w8 = 0; w8 < 8; w8++) tot += red[w8];
    float inv = 1.0f / tot;
    for (int e0 = tid; e0 < E; e0 += 256) {
        float acc = 0;
        for (int t = 0; t < T; t++) acc += s[t] * hb[(long)t * E + e0];
        g_pool[(long)b * E + e0] = acc * inv;
    }
}

// ---------------- warp-per-output GEMV ----------------
__global__ void gemv_warp(const float* __restrict__ A, const float* __restrict__ W,
                          const float* __restrict__ bias, float* __restrict__ C,
                          int M, int N, int Kd) {
    int gw = (blockIdx.x * blockDim.x + threadIdx.x) >> 5;
    int lane = threadIdx.x & 31;
    if (gw >= M * N) return;
    int m = gw / N, n = gw % N;
    const float* a = A + (long)m * Kd;
    const float* w = W + (long)n * Kd;
    float acc = 0;
    for (int i = lane; i < Kd; i += 32) acc += a[i] * w[i];
    #pragma unroll
    for (int o = 16; o; o >>= 1) acc += __shfl_xor_sync(~0u, acc, o);
    if (lane == 0) C[(long)m * N + n] = acc + (bias ? bias[n] : 0.0f);
}

// ---------------- final head ----------------
__global__ void head2_kernel(const float* __restrict__ w2, const float* __restrict__ b2,
                             float* __restrict__ out) {
    int b = blockIdx.x;
    int lane = threadIdx.x;
    float acc = 0;
    for (int i = lane; i < HID; i += 32) acc += fmaxf(g_o1[(long)b * HID + i], 0.0f) * w2[i];
    #pragma unroll
    for (int o = 16; o; o >>= 1) acc += __shfl_xor_sync(~0u, acc, o);
    if (lane == 0) out[b] = acc + b2[0];
}

// ---------------- host ----------------
extern "C" void kernel_launch(void* const* d_in, const int* in_sizes, int n_in,
                              void* d_out, int out_size) {
    const float* tok_emb = (const float*)d_in[0];
    const float* pos_emb = (const float*)d_in[1];
    const float* ln1_w = (const float*)d_in[2];
    const float* ln1_b = (const float*)d_in[3];
    const float* ln2_w = (const float*)d_in[4];
    const float* ln2_b = (const float*)d_in[5];
    const float* qkv_w = (const float*)d_in[6];
    const float* out_w = (const float*)d_in[7];
    const float* route_w = (const float*)d_in[8];
    const float* route_b = (const float*)d_in[9];
    const float* noise_w = (const float*)d_in[10];
    const float* noise_b = (const float*)d_in[11];
    const float* exp_w1 = (const float*)d_in[12];
    const float* exp_b1 = (const float*)d_in[13];
    const float* exp_w2 = (const float*)d_in[14];
    const float* exp_b2 = (const float*)d_in[15];
    const float* lnf_w = (const float*)d_in[16];
    const float* lnf_b = (const float*)d_in[17];
    const float* pool_q = (const float*)d_in[18];
    const float* pool_w = (const float*)d_in[19];
    const float* pool_b = (const float*)d_in[20];
    const float* head_w1 = (const float*)d_in[21];
    const float* head_b1 = (const float*)d_in[22];
    const float* head_w2 = (const float*)d_in[23];
    const float* head_b2 = (const float*)d_in[24];
    const int* ids = (const int*)d_in[25];
    const float* rnoise = (const float*)d_in[26];
    float* out = (float*)d_out;

    float *px, *ph, *pqkv, *patt, *pein, *pehid, *peout, *ppool, *phv, *po1;
    cudaGetSymbolAddress((void**)&px, g_x);
    cudaGetSymbolAddress((void**)&ph, g_h);
    cudaGetSymbolAddress((void**)&pqkv, g_qkv);
    cudaGetSymbolAddress((void**)&patt, g_att);
    cudaGetSymbolAddress((void**)&pein, g_ein);
    cudaGetSymbolAddress((void**)&pehid, g_ehid);
    cudaGetSymbolAddress((void**)&peout, g_eout);
    cudaGetSymbolAddress((void**)&ppool, g_pool);
    cudaGetSymbolAddress((void**)&phv, g_hv);
    cudaGetSymbolAddress((void**)&po1, g_o1);

    embed_kernel<<<NTOK, 128>>>(tok_emb, pos_emb, ids);

    for (int l = 0; l < NL; l++) {
        ln_kernel<<<NTOK, 256>>>(px, ln1_w + l * E, ln1_b + l * E, ph);
        {
            dim3 g(3 * E / 128, NTOK / 128, 1);
            gemm_kernel<<<g, 256>>>(ph, qkv_w + (long)l * 3 * E * E, nullptr, nullptr,
                                    pqkv, NTOK, 3 * E, E, 0, 0, 0, 0, 0);
        }
        rope_kernel<<<NTOK, 512>>>();
        attn_kernel<<<BB * HN * T / 8, 256>>>();
        {
            dim3 g(E / 128, NTOK / 128, 1);
            gemm_kernel<<<g, 256>>>(patt, out_w + (long)l * E * E, nullptr, px,
                                    px, NTOK, E, E, 0, 0, 0, 0, 0);
        }
        ln_kernel<<<NTOK, 256>>>(px, ln2_w + l * E, ln2_b + l * E, ph);
        router_kernel<<<NTOK / 8, 256>>>(route_w + (long)l * X * E, route_b + l * X,
                                         noise_w + (long)l * X * E, noise_b + l * X,
                                         rnoise + (long)l * NTOK * X);
        dispatch_kernel<<<X, 256>>>();
        gather_kernel<<<X * CAP, 128>>>();
        {
            dim3 g1(H4 / 128, CAP / 128, X);
            gemm_kernel<<<g1, 256>>>(pein, exp_w1 + (long)l * X * H4 * E,
                                     exp_b1 + (long)l * X * H4, nullptr, pehid,
                                     CAP, H4, E, CAP * E, H4 * E, H4, CAP * H4, 1);
            dim3 g2(E / 128, CAP / 128, X);
            gemm_kernel<<<g2, 256>>>(pehid, exp_w2 + (long)l * X * E * H4,
                                     exp_b2 + (long)l * X * E, nullptr, peout,
                                     CAP, E, H4, CAP * H4, E * H4, E, CAP * E, 0);
        }
        combine_kernel<<<NTOK, 128>>>();
    }

    ln_kernel<<<NTOK, 256>>>(px, lnf_w, lnf_b, ph);
    pool_kernel<<<BB, 256>>>(pool_q);
    gemv_warp<<<(BB * HIGH * 32) / 256, 256>>>(ppool, pool_w, pool_b, phv, BB, HIGH, E);
    gemv_warp<<<(BB * HID * 32) / 256, 256>>>(phv, head_w1, head_b1, po1, BB, HID, HIGH);
    head2_kernel<<<BB, 32>>>(head_w2, head_b2, out);
}

// round 5
// speedup vs baseline: 1.1441x; 1.1441x over previous
#include <cuda_runtime.h>
#include <math.h>
#include <stdint.h>

#define E 512
#define T 1024
#define BB 8
#define HN 8
#define DH 64
#define HALF 32
#define NL 4
#define X 8
#define TOPK 2
#define CAP 2048
#define H4 2048
#define NTOK 8192
#define HIGH 32000
#define HID 1024

// ---------------- scratch (device globals; no allocation allowed) ----------------
__device__ float g_x[NTOK * E];
__device__ float g_h[NTOK * E];
__device__ float g_qkv[NTOK * 3 * E];
__device__ float g_att[NTOK * E];
__device__ int   g_topi[NTOK * TOPK];
__device__ float g_gatev[NTOK * TOPK];
__device__ int   g_idx[X * CAP];
__device__ float g_gate[X * CAP];
__device__ int   g_slot[NTOK * TOPK];
__device__ int   g_cnt[X];
__device__ float g_ein[X * CAP * E];
__device__ float g_ehid[(long)X * CAP * H4];
__device__ float g_eout[X * CAP * E];
__device__ float g_pool[BB * E];
__device__ float g_hv[BB * HIGH];
__device__ float g_o1[BB * HID];

// ---------------- embed ----------------
__global__ void embed_kernel(const float* __restrict__ tok, const float* __restrict__ pos,
                             const int* __restrict__ ids) {
    int n = blockIdx.x;
    int t = n % T;
    int id = ids[n];
    const float4* te = (const float4*)(tok + (long)id * E);
    const float4* pe = (const float4*)(pos + (long)t * E);
    float4* xr = (float4*)(g_x + (long)n * E);
    int i = threadIdx.x;
    float4 a = te[i], b = pe[i];
    a.x += b.x; a.y += b.y; a.z += b.z; a.w += b.w;
    xr[i] = a;
}

// ---------------- layernorm ----------------
__global__ void ln_kernel(const float* __restrict__ in, const float* __restrict__ w,
                          const float* __restrict__ b, float* __restrict__ out) {
    int n = blockIdx.x;
    int tid = threadIdx.x, lane = tid & 31, wid = tid >> 5;
    __shared__ float red[8];
    const float* r = in + (long)n * E;
    float v0 = r[tid], v1 = r[tid + 256];
    float s = v0 + v1;
    #pragma unroll
    for (int o = 16; o; o >>= 1) s += __shfl_xor_sync(~0u, s, o);
    if (lane == 0) red[wid] = s;
    __syncthreads();
    float tot = 0;
    #pragma unroll
    for (int w8 = 0; w8 < 8; w8++) tot += red[w8];
    float mean = tot * (1.0f / E);
    float d0 = v0 - mean, d1 = v1 - mean;
    float sq = d0 * d0 + d1 * d1;
    __syncthreads();
    #pragma unroll
    for (int o = 16; o; o >>= 1) sq += __shfl_xor_sync(~0u, sq, o);
    if (lane == 0) red[wid] = sq;
    __syncthreads();
    float tv = 0;
    #pragma unroll
    for (int w8 = 0; w8 < 8; w8++) tv += red[w8];
    float inv = rsqrtf(tv * (1.0f / E) + 1e-5f);
    out[(long)n * E + tid] = d0 * inv * w[tid] + b[tid];
    out[(long)n * E + tid + 256] = d1 * inv * w[tid + 256] + b[tid + 256];
}

// ---------------- tf32 helpers ----------------
__device__ __forceinline__ float tf32r(float x) {
    uint32_t u;
    asm("cvt.rna.tf32.f32 %0, %1;" : "=r"(u) : "f"(x));
    return __uint_as_float(u);
}

__device__ __forceinline__ void mma_tf32(float c[4], uint32_t a0, uint32_t a1,
                                         uint32_t a2, uint32_t a3,
                                         uint32_t b0, uint32_t b1) {
    asm volatile(
        "mma.sync.aligned.m16n8k8.row.col.f32.tf32.tf32.f32 "
        "{%0,%1,%2,%3}, {%4,%5,%6,%7}, {%8,%9}, {%0,%1,%2,%3};"
        : "+f"(c[0]), "+f"(c[1]), "+f"(c[2]), "+f"(c[3])
        : "r"(a0), "r"(a1), "r"(a2), "r"(a3), "r"(b0), "r"(b1));
}

// ---------------- 3xTF32 tensor-core GEMM: C = act(A @ W^T + bias [+resid]) ----------------
// A [M,Kd] row-major, W [N,Kd] row-major. 128x128x16 tiles, 256 threads,
// warp grid 2(M)x4(N), warp tile 64x32 via m16n8k8, hi/lo split for ~fp32 precision.
#define SKP 20
__global__ void __launch_bounds__(256, 2)
gemm_tf32(const float* __restrict__ A, const float* __restrict__ W,
          const float* __restrict__ bias, const float* __restrict__ resid,
          float* __restrict__ C, int M, int N, int Kd,
          int aB, int wB, int bB, int cB, int act) {
    int z = blockIdx.z;
    A += (long)z * aB;
    W += (long)z * wB;
    C += (long)z * cB;
    __shared__ float AsH[128][SKP];
    __shared__ float AsL[128][SKP];
    __shared__ float WsH[128][SKP];
    __shared__ float WsL[128][SKP];
    int tid = threadIdx.x;
    int lane = tid & 31, w = tid >> 5;
    int g = lane >> 2, tig = lane & 3;
    int wm = (w >> 2) * 64, wn = (w & 3) * 32;
    int m0 = blockIdx.y * 128, n0 = blockIdx.x * 128;
    float c[4][4][4] = {};

    for (int k0 = 0; k0 < Kd; k0 += 16) {
        #pragma unroll
        for (int i = 0; i < 2; i++) {
            int f = tid + 256 * i;            // 0..511
            int row = f >> 2, kc = (f & 3) * 4;
            float4 va = *(const float4*)(A + (long)(m0 + row) * Kd + k0 + kc);
            float4 vw = *(const float4*)(W + (long)(n0 + row) * Kd + k0 + kc);
            float4 ah, al, wh, wl;
            ah.x = tf32r(va.x); al.x = tf32r(va.x - ah.x);
            ah.y = tf32r(va.y); al.y = tf32r(va.y - ah.y);
            ah.z = tf32r(va.z); al.z = tf32r(va.z - ah.z);
            ah.w = tf32r(va.w); al.w = tf32r(va.w - ah.w);
            wh.x = tf32r(vw.x); wl.x = tf32r(vw.x - wh.x);
            wh.y = tf32r(vw.y); wl.y = tf32r(vw.y - wh.y);
            wh.z = tf32r(vw.z); wl.z = tf32r(vw.z - wh.z);
            wh.w = tf32r(vw.w); wl.w = tf32r(vw.w - wh.w);
            *(float4*)&AsH[row][kc] = ah;
            *(float4*)&AsL[row][kc] = al;
            *(float4*)&WsH[row][kc] = wh;
            *(float4*)&WsL[row][kc] = wl;
        }
        __syncthreads();
        #pragma unroll
        for (int ks = 0; ks < 2; ks++) {
            int kb = ks * 8;
            uint32_t aH[4][4], aL[4][4];
            #pragma unroll
            for (int mf = 0; mf < 4; mf++) {
                int r = wm + mf * 16 + g;
                aH[mf][0] = __float_as_uint(AsH[r][kb + tig]);
                aH[mf][1] = __float_as_uint(AsH[r + 8][kb + tig]);
                aH[mf][2] = __float_as_uint(AsH[r][kb + tig + 4]);
                aH[mf][3] = __float_as_uint(AsH[r + 8][kb + tig + 4]);
                aL[mf][0] = __float_as_uint(AsL[r][kb + tig]);
                aL[mf][1] = __float_as_uint(AsL[r + 8][kb + tig]);
                aL[mf][2] = __float_as_uint(AsL[r][kb + tig + 4]);
                aL[mf][3] = __float_as_uint(AsL[r + 8][kb + tig + 4]);
            }
            #pragma unroll
            for (int nf = 0; nf < 4; nf++) {
                int r = wn + nf * 8 + g;
                uint32_t bH0 = __float_as_uint(WsH[r][kb + tig]);
                uint32_t bH1 = __float_as_uint(WsH[r][kb + tig + 4]);
                uint32_t bL0 = __float_as_uint(WsL[r][kb + tig]);
                uint32_t bL1 = __float_as_uint(WsL[r][kb + tig + 4]);
                #pragma unroll
                for (int mf = 0; mf < 4; mf++) {
                    mma_tf32(c[mf][nf], aL[mf][0], aL[mf][1], aL[mf][2], aL[mf][3], bH0, bH1);
                    mma_tf32(c[mf][nf], aH[mf][0], aH[mf][1], aH[mf][2], aH[mf][3], bL0, bL1);
                    mma_tf32(c[mf][nf], aH[mf][0], aH[mf][1], aH[mf][2], aH[mf][3], bH0, bH1);
                }
            }
        }
        __syncthreads();
    }

    #pragma unroll
    for (int mf = 0; mf < 4; mf++) {
        #pragma unroll
        for (int nf = 0; nf < 4; nf++) {
            int mbase = m0 + wm + mf * 16 + g;
            int nbase = n0 + wn + nf * 8 + tig * 2;
            #pragma unroll
            for (int i = 0; i < 2; i++) {
                #pragma unroll
                for (int j = 0; j < 2; j++) {
                    int m = mbase + i * 8;
                    int n = nbase + j;
                    float v = c[mf][nf][i * 2 + j];
                    if (bias) v += bias[(long)z * bB + n];
                    if (resid) v += resid[(long)m * N + n];
                    if (act) v = fmaxf(v, 0.0f);
                    C[(long)m * N + n] = v;
                }
            }
        }
    }
}

// ---------------- RoPE in-place on q,k of g_qkv ----------------
__global__ void rope_kernel() {
    int n = blockIdx.x;
    int tid = threadIdx.x;  // 512
    int which = tid >> 8;
    int rem = tid & 255;
    int h = rem >> 5, j = rem & 31;
    int t = n % T;
    float div = expf(-(float)j * (9.210340371976184f / 32.0f));
    float ang = (float)t * div;
    float c = cosf(ang), s = sinf(ang);
    float* p = g_qkv + (long)n * 3 * E + which * E + h * DH;
    float a1 = p[j], a2 = p[j + HALF];
    p[j] = a1 * c - a2 * s;
    p[j + HALF] = a2 * c + a1 * s;
}

// ---------------- attention: one warp per (b,h,t), online softmax ----------------
// Output written in the reference's permuted layout:
// row t' = h*128 + t/8, channel e' = (t%8)*64 + d.
__global__ void attn_kernel() {
    int gw = (blockIdx.x * blockDim.x + threadIdx.x) >> 5;
    int lane = threadIdx.x & 31;
    int b = gw >> 13;
    int rem = gw & 8191;
    int h = rem >> 10;
    int t = rem & 1023;
    int n = b * T + t;
    const float* qr = g_qkv + (long)n * 3 * E + h * DH;
    float q0 = qr[lane] * 0.125f, q1 = qr[lane + 32] * 0.125f;
    float m = -INFINITY, lsum = 0.0f, a0 = 0.0f, a1 = 0.0f;
    const float* kbase = g_qkv + (long)b * T * 3 * E + E + h * DH;
    for (int s = 0; s < T; s++) {
        const float* kr = kbase + (long)s * 3 * E;
        float p = q0 * kr[lane] + q1 * kr[lane + 32];
        #pragma unroll
        for (int o = 16; o; o >>= 1) p += __shfl_xor_sync(~0u, p, o);
        float mn = fmaxf(m, p);
        float corr = expf(m - mn);
        float w = expf(p - mn);
        lsum = lsum * corr + w;
        const float* vr = kr + E;
        a0 = a0 * corr + w * vr[lane];
        a1 = a1 * corr + w * vr[lane + 32];
        m = mn;
    }
    float inv = 1.0f / lsum;
    int tp = h * 128 + (t >> 3);
    int ep = (t & 7) * 64;
    float* orow = g_att + ((long)b * T + tp) * E + ep;
    orow[lane] = a0 * inv;
    orow[lane + 32] = a1 * inv;
}

// ---------------- router: warp per token, top-2 + gates ----------------
__global__ void router_kernel(const float* __restrict__ rw, const float* __restrict__ rb,
                              const float* __restrict__ nw, const float* __restrict__ nb,
                              const float* __restrict__ rn) {
    int gw = (blockIdx.x * blockDim.x + threadIdx.x) >> 5;
    int lane = threadIdx.x & 31;
    if (gw >= NTOK) return;
    const float* h = g_h + (long)gw * E;
    float hr[16];
    #pragma unroll
    for (int j = 0; j < 16; j++) hr[j] = h[lane + 32 * j];
    float lg[X], ng[X];
    #pragma unroll
    for (int e = 0; e < X; e++) {
        float a = 0, bn = 0;
        const float* wr = rw + (long)e * E;
        const float* wn = nw + (long)e * E;
        #pragma unroll
        for (int j = 0; j < 16; j++) {
            a += hr[j] * wr[lane + 32 * j];
            bn += hr[j] * wn[lane + 32 * j];
        }
        #pragma unroll
        for (int o = 16; o; o >>= 1) {
            a += __shfl_xor_sync(~0u, a, o);
            bn += __shfl_xor_sync(~0u, bn, o);
        }
        lg[e] = a;
        ng[e] = bn;
    }
    if (lane == 0) {
        float noisy[X];
        #pragma unroll
        for (int e = 0; e < X; e++) {
            float lo = lg[e] + rb[e];
            float nl = ng[e] + nb[e];
            float sp = nl > 0.0f ? nl + log1pf(expf(-nl)) : log1pf(expf(nl));
            noisy[e] = lo + rn[(long)gw * X + e] * sp;
        }
        int b1 = 0; float v1 = noisy[0];
        #pragma unroll
        for (int e = 1; e < X; e++) if (noisy[e] > v1) { v1 = noisy[e]; b1 = e; }
        int b2 = -1; float v2 = -INFINITY;
        #pragma unroll
        for (int e = 0; e < X; e++) if (e != b1 && noisy[e] > v2) { v2 = noisy[e]; b2 = e; }
        float zz = expf(v2 - v1);
        float p1 = 1.0f / (1.0f + zz);
        float p2 = zz / (1.0f + zz);
        g_topi[gw * 2] = b1; g_topi[gw * 2 + 1] = b2;
        g_gatev[gw * 2] = p1; g_gatev[gw * 2 + 1] = p2;
    }
}

// ---------------- dispatch: ordered compaction per expert ----------------
__global__ void dispatch_kernel() {
    int e = blockIdx.x;
    int tid = threadIdx.x, lane = tid & 31, wid = tid >> 5;
    __shared__ int wsum[8];
    __shared__ int sbase;
    if (tid == 0) sbase = 0;
    __syncthreads();
    for (int c = 0; c < NTOK; c += 256) {
        int n = c + tid;
        int k = -1;
        if (g_topi[n * 2] == e) k = 0;
        else if (g_topi[n * 2 + 1] == e) k = 1;
        unsigned bal = __ballot_sync(~0u, k >= 0);
        if (lane == 0) wsum[wid] = __popc(bal);
        __syncthreads();
        int pre = 0, total = 0;
        #pragma unroll
        for (int w8 = 0; w8 < 8; w8++) {
            total += wsum[w8];
            if (w8 < wid) pre += wsum[w8];
        }
        if (k >= 0) {
            int pos = sbase + pre + __popc(bal & ((1u << lane) - 1));
            if (pos < CAP) {
                g_idx[e * CAP + pos] = n;
                g_gate[e * CAP + pos] = g_gatev[n * 2 + k];
                g_slot[n * 2 + k] = e * CAP + pos;
            } else {
                g_slot[n * 2 + k] = -1;
            }
        }
        __syncthreads();
        if (tid == 0) sbase += total;
        __syncthreads();
    }
    if (tid == 0) g_cnt[e] = sbase < CAP ? sbase : CAP;
}

// ---------------- gather expert inputs ----------------
__global__ void gather_kernel() {
    int r = blockIdx.x;
    int e = r / CAP, s = r % CAP;
    float4* dst = (float4*)(g_ein + (long)r * E);
    int i = threadIdx.x;
    if (s < g_cnt[e]) {
        const float4* src = (const float4*)(g_h + (long)g_idx[r] * E);
        dst[i] = src[i];
    } else {
        float4 zf = {0, 0, 0, 0};
        dst[i] = zf;
    }
}

// ---------------- combine ----------------
__global__ void combine_kernel() {
    int n = blockIdx.x;
    int i = threadIdx.x;
    float4* xr = (float4*)(g_x + (long)n * E);
    float4 v = xr[i];
    #pragma unroll
    for (int k = 0; k < 2; k++) {
        int s = g_slot[n * 2 + k];
        if (s >= 0) {
            float g = g_gate[s];
            float4 eo = ((const float4*)(g_eout + (long)s * E))[i];
            v.x += g * eo.x; v.y += g * eo.y; v.z += g * eo.z; v.w += g * eo.w;
        }
    }
    xr[i] = v;
}

// ---------------- attention pooling ----------------
__global__ void pool_kernel(const float* __restrict__ pq) {
    int b = blockIdx.x;
    int tid = threadIdx.x, lane = tid & 31, wid = tid >> 5;
    __shared__ float s[T];
    __shared__ float red[8];
    const float* hb = g_h + (long)b * T * E;
    for (int t = wid; t < T; t += 8) {
        float acc = 0;
        const float* row = hb + (long)t * E;
        for (int i = lane; i < E; i += 32) acc += pq[i] * row[i];
        #pragma unroll
        for (int o = 16; o; o >>= 1) acc += __shfl_xor_sync(~0u, acc, o);
        if (lane == 0) s[t] = acc * (1.0f / 22.627416997969522f);
    }
    __syncthreads();
    float m = -INFINITY;
    for (int t = tid; t < T; t += 256) m = fmaxf(m, s[t]);
    #pragma unroll
    for (int o = 16; o; o >>= 1) m = fmaxf(m, __shfl_xor_sync(~0u, m, o));
    if (lane == 0) red[wid] = m;
    __syncthreads();
    float mm = red[0];
    #pragma unroll
    for (int w8 = 1; w8 < 8; w8++) mm = fmaxf(mm, red[w8]);
    float sum = 0;
    for (int t = tid; t < T; t += 256) {
        float e2 = expf(s[t] - mm);
        s[t] = e2;
        sum += e2;
    }
    #pragma unroll
    for (int o = 16; o; o >>= 1) sum += __shfl_xor_sync(~0u, sum, o);
    __syncthreads();
    if (lane == 0) red[wid] = sum;
    __syncthreads();
    float tot = 0;
    #pragma unroll
    for (int w8 = 0; w8 < 8; w8++) tot += red[w8];
    float inv = 1.0f / tot;
    for (int e0 = tid; e0 < E; e0 += 256) {
        float acc = 0;
        for (int t = 0; t < T; t++) acc += s[t] * hb[(long)t * E + e0];
        g_pool[(long)b * E + e0] = acc * inv;
    }
}

// ---------------- warp-per-output GEMV ----------------
__global__ void gemv_warp(const float* __restrict__ A, const float* __restrict__ W,
                          const float* __restrict__ bias, float* __restrict__ C,
                          int M, int N, int Kd) {
    int gw = (blockIdx.x * blockDim.x + threadIdx.x) >> 5;
    int lane = threadIdx.x & 31;
    if (gw >= M * N) return;
    int m = gw / N, n = gw % N;
    const float* a = A + (long)m * Kd;
    const float* w = W + (long)n * Kd;
    float acc = 0;
    for (int i = lane; i < Kd; i += 32) acc += a[i] * w[i];
    #pragma unroll
    for (int o = 16; o; o >>= 1) acc += __shfl_xor_sync(~0u, acc, o);
    if (lane == 0) C[(long)m * N + n] = acc + (bias ? bias[n] : 0.0f);
}

// ---------------- final head ----------------
__global__ void head2_kernel(const float* __restrict__ w2, const float* __restrict__ b2,
                             float* __restrict__ out) {
    int b = blockIdx.x;
    int lane = threadIdx.x;
    float acc = 0;
    for (int i = lane; i < HID; i += 32) acc += fmaxf(g_o1[(long)b * HID + i], 0.0f) * w2[i];
    #pragma unroll
    for (int o = 16; o; o >>= 1) acc += __shfl_xor_sync(~0u, acc, o);
    if (lane == 0) out[b] = acc + b2[0];
}

// ---------------- host ----------------
extern "C" void kernel_launch(void* const* d_in, const int* in_sizes, int n_in,
                              void* d_out, int out_size) {
    const float* tok_emb = (const float*)d_in[0];
    const float* pos_emb = (const float*)d_in[1];
    const float* ln1_w = (const float*)d_in[2];
    const float* ln1_b = (const float*)d_in[3];
    const float* ln2_w = (const float*)d_in[4];
    const float* ln2_b = (const float*)d_in[5];
    const float* qkv_w = (const float*)d_in[6];
    const float* out_w = (const float*)d_in[7];
    const float* route_w = (const float*)d_in[8];
    const float* route_b = (const float*)d_in[9];
    const float* noise_w = (const float*)d_in[10];
    const float* noise_b = (const float*)d_in[11];
    const float* exp_w1 = (const float*)d_in[12];
    const float* exp_b1 = (const float*)d_in[13];
    const float* exp_w2 = (const float*)d_in[14];
    const float* exp_b2 = (const float*)d_in[15];
    const float* lnf_w = (const float*)d_in[16];
    const float* lnf_b = (const float*)d_in[17];
    const float* pool_q = (const float*)d_in[18];
    const float* pool_w = (const float*)d_in[19];
    const float* pool_b = (const float*)d_in[20];
    const float* head_w1 = (const float*)d_in[21];
    const float* head_b1 = (const float*)d_in[22];
    const float* head_w2 = (const float*)d_in[23];
    const float* head_b2 = (const float*)d_in[24];
    const int* ids = (const int*)d_in[25];
    const float* rnoise = (const float*)d_in[26];
    float* out = (float*)d_out;

    float *px, *ph, *pqkv, *patt, *pein, *pehid, *peout, *ppool, *phv, *po1;
    cudaGetSymbolAddress((void**)&px, g_x);
    cudaGetSymbolAddress((void**)&ph, g_h);
    cudaGetSymbolAddress((void**)&pqkv, g_qkv);
    cudaGetSymbolAddress((void**)&patt, g_att);
    cudaGetSymbolAddress((void**)&pein, g_ein);
    cudaGetSymbolAddress((void**)&pehid, g_ehid);
    cudaGetSymbolAddress((void**)&peout, g_eout);
    cudaGetSymbolAddress((void**)&ppool, g_pool);
    cudaGetSymbolAddress((void**)&phv, g_hv);
    cudaGetSymbolAddress((void**)&po1, g_o1);

    embed_kernel<<<NTOK, 128>>>(tok_emb, pos_emb, ids);

    for (int l = 0; l < NL; l++) {
        ln_kernel<<<NTOK, 256>>>(px, ln1_w + l * E, ln1_b + l * E, ph);
        {
            dim3 g(3 * E / 128, NTOK / 128, 1);
            gemm_tf32<<<g, 256>>>(ph, qkv_w + (long)l * 3 * E * E, nullptr, nullptr,
                                  pqkv, NTOK, 3 * E, E, 0, 0, 0, 0, 0);
        }
        rope_kernel<<<NTOK, 512>>>();
        attn_kernel<<<BB * HN * T / 8, 256>>>();
        {
            dim3 g(E / 128, NTOK / 128, 1);
            gemm_tf32<<<g, 256>>>(patt, out_w + (long)l * E * E, nullptr, px,
                                  px, NTOK, E, E, 0, 0, 0, 0, 0);
        }
        ln_kernel<<<NTOK, 256>>>(px, ln2_w + l * E, ln2_b + l * E, ph);
        router_kernel<<<NTOK / 8, 256>>>(route_w + (long)l * X * E, route_b + l * X,
                                         noise_w + (long)l * X * E, noise_b + l * X,
                                         rnoise + (long)l * NTOK * X);
        dispatch_kernel<<<X, 256>>>();
        gather_kernel<<<X * CAP, 128>>>();
        {
            dim3 g1(H4 / 128, CAP / 128, X);
            gemm_tf32<<<g1, 256>>>(pein, exp_w1 + (long)l * X * H4 * E,
                                   exp_b1 + (long)l * X * H4, nullptr, pehid,
                                   CAP, H4, E, CAP * E, H4 * E, H4, CAP * H4, 1);
            dim3 g2(E / 128, CAP / 128, X);
            gemm_tf32<<<g2, 256>>>(pehid, exp_w2 + (long)l * X * E * H4,
                                   exp_b2 + (long)l * X * E, nullptr, peout,
                                   CAP, E, H4, CAP * H4, E * H4, E, CAP * E, 0);
        }
        combine_kernel<<<NTOK, 128>>>();
    }

    ln_kernel<<<NTOK, 256>>>(px, lnf_w, lnf_b, ph);
    pool_kernel<<<BB, 256>>>(pool_q);
    gemv_warp<<<(BB * HIGH * 32) / 256, 256>>>(ppool, pool_w, pool_b, phv, BB, HIGH, E);
    gemv_warp<<<(BB * HID * 32) / 256, 256>>>(phv, head_w1, head_b1, po1, BB, HID, HIGH);
    head2_kernel<<<BB, 32>>>(head_w2, head_b2, out);
}

// round 7
// speedup vs baseline: 1.8346x; 1.6036x over previous
#include <cuda_runtime.h>
#include <math.h>
#include <stdint.h>

#define E 512
#define T 1024
#define BB 8
#define HN 8
#define DH 64
#define HALF 32
#define NL 4
#define X 8
#define TOPK 2
#define CAP 2048
#define H4 2048
#define NTOK 8192
#define HIGH 32000
#define HID 1024

// ---------------- scratch (device globals; no allocation allowed) ----------------
__device__ float g_x[NTOK * E];
__device__ float g_h[NTOK * E];
__device__ float g_qkv[NTOK * 3 * E];
__device__ float g_att[NTOK * E];
__device__ int   g_topi[NTOK * TOPK];
__device__ float g_gatev[NTOK * TOPK];
__device__ int   g_idx[X * CAP];
__device__ float g_gate[X * CAP];
__device__ int   g_slot[NTOK * TOPK];
__device__ int   g_cnt[X];
__device__ float g_ein[X * CAP * E];
__device__ float g_ehid[(long)X * CAP * H4];
__device__ float g_eout[X * CAP * E];
__device__ float g_pool[BB * E];
__device__ float g_hv[BB * HIGH];
__device__ float g_o1[BB * HID];

// ---------------- embed ----------------
__global__ void embed_kernel(const float* __restrict__ tok, const float* __restrict__ pos,
                             const int* __restrict__ ids) {
    int n = blockIdx.x;
    int t = n % T;
    int id = ids[n];
    const float4* te = (const float4*)(tok + (long)id * E);
    const float4* pe = (const float4*)(pos + (long)t * E);
    float4* xr = (float4*)(g_x + (long)n * E);
    int i = threadIdx.x;
    float4 a = te[i], b = pe[i];
    a.x += b.x; a.y += b.y; a.z += b.z; a.w += b.w;
    xr[i] = a;
}

// ---------------- layernorm ----------------
__global__ void ln_kernel(const float* __restrict__ in, const float* __restrict__ w,
                          const float* __restrict__ b, float* __restrict__ out) {
    int n = blockIdx.x;
    int tid = threadIdx.x, lane = tid & 31, wid = tid >> 5;
    __shared__ float red[8];
    const float* r = in + (long)n * E;
    float v0 = r[tid], v1 = r[tid + 256];
    float s = v0 + v1;
    #pragma unroll
    for (int o = 16; o; o >>= 1) s += __shfl_xor_sync(~0u, s, o);
    if (lane == 0) red[wid] = s;
    __syncthreads();
    float tot = 0;
    #pragma unroll
    for (int w8 = 0; w8 < 8; w8++) tot += red[w8];
    float mean = tot * (1.0f / E);
    float d0 = v0 - mean, d1 = v1 - mean;
    float sq = d0 * d0 + d1 * d1;
    __syncthreads();
    #pragma unroll
    for (int o = 16; o; o >>= 1) sq += __shfl_xor_sync(~0u, sq, o);
    if (lane == 0) red[wid] = sq;
    __syncthreads();
    float tv = 0;
    #pragma unroll
    for (int w8 = 0; w8 < 8; w8++) tv += red[w8];
    float inv = rsqrtf(tv * (1.0f / E) + 1e-5f);
    out[(long)n * E + tid] = d0 * inv * w[tid] + b[tid];
    out[(long)n * E + tid + 256] = d1 * inv * w[tid + 256] + b[tid + 256];
}

// ---------------- tf32 helpers ----------------
__device__ __forceinline__ float tf32r(float x) {
    uint32_t u;
    asm("cvt.rna.tf32.f32 %0, %1;" : "=r"(u) : "f"(x));
    return __uint_as_float(u);
}

__device__ __forceinline__ void mma_tf32(float c[4], uint32_t a0, uint32_t a1,
                                         uint32_t a2, uint32_t a3,
                                         uint32_t b0, uint32_t b1) {
    asm volatile(
        "mma.sync.aligned.m16n8k8.row.col.f32.tf32.tf32.f32 "
        "{%0,%1,%2,%3}, {%4,%5,%6,%7}, {%8,%9}, {%0,%1,%2,%3};"
        : "+f"(c[0]), "+f"(c[1]), "+f"(c[2]), "+f"(c[3])
        : "r"(a0), "r"(a1), "r"(a2), "r"(a3), "r"(b0), "r"(b1));
}

// ---------------- 3xTF32 tensor-core GEMM: C = act(A @ W^T + bias [+resid]) ----------------
#define SKP 20
__global__ void __launch_bounds__(256, 2)
gemm_tf32(const float* __restrict__ A, const float* __restrict__ W,
          const float* __restrict__ bias, const float* __restrict__ resid,
          float* __restrict__ C, int M, int N, int Kd,
          int aB, int wB, int bB, int cB, int act) {
    int z = blockIdx.z;
    A += (long)z * aB;
    W += (long)z * wB;
    C += (long)z * cB;
    __shared__ float AsH[128][SKP];
    __shared__ float AsL[128][SKP];
    __shared__ float WsH[128][SKP];
    __shared__ float WsL[128][SKP];
    int tid = threadIdx.x;
    int lane = tid & 31, w = tid >> 5;
    int g = lane >> 2, tig = lane & 3;
    int wm = (w >> 2) * 64, wn = (w & 3) * 32;
    int m0 = blockIdx.y * 128, n0 = blockIdx.x * 128;
    float c[4][4][4] = {};

    for (int k0 = 0; k0 < Kd; k0 += 16) {
        #pragma unroll
        for (int i = 0; i < 2; i++) {
            int f = tid + 256 * i;
            int row = f >> 2, kc = (f & 3) * 4;
            float4 va = *(const float4*)(A + (long)(m0 + row) * Kd + k0 + kc);
            float4 vw = *(const float4*)(W + (long)(n0 + row) * Kd + k0 + kc);
            float4 ah, al, wh, wl;
            ah.x = tf32r(va.x); al.x = tf32r(va.x - ah.x);
            ah.y = tf32r(va.y); al.y = tf32r(va.y - ah.y);
            ah.z = tf32r(va.z); al.z = tf32r(va.z - ah.z);
            ah.w = tf32r(va.w); al.w = tf32r(va.w - ah.w);
            wh.x = tf32r(vw.x); wl.x = tf32r(vw.x - wh.x);
            wh.y = tf32r(vw.y); wl.y = tf32r(vw.y - wh.y);
            wh.z = tf32r(vw.z); wl.z = tf32r(vw.z - wh.z);
            wh.w = tf32r(vw.w); wl.w = tf32r(vw.w - wh.w);
            *(float4*)&AsH[row][kc] = ah;
            *(float4*)&AsL[row][kc] = al;
            *(float4*)&WsH[row][kc] = wh;
            *(float4*)&WsL[row][kc] = wl;
        }
        __syncthreads();
        #pragma unroll
        for (int ks = 0; ks < 2; ks++) {
            int kb = ks * 8;
            uint32_t aH[4][4], aL[4][4];
            #pragma unroll
            for (int mf = 0; mf < 4; mf++) {
                int r = wm + mf * 16 + g;
                aH[mf][0] = __float_as_uint(AsH[r][kb + tig]);
                aH[mf][1] = __float_as_uint(AsH[r + 8][kb + tig]);
                aH[mf][2] = __float_as_uint(AsH[r][kb + tig + 4]);
                aH[mf][3] = __float_as_uint(AsH[r + 8][kb + tig + 4]);
                aL[mf][0] = __float_as_uint(AsL[r][kb + tig]);
                aL[mf][1] = __float_as_uint(AsL[r + 8][kb + tig]);
                aL[mf][2] = __float_as_uint(AsL[r][kb + tig + 4]);
                aL[mf][3] = __float_as_uint(AsL[r + 8][kb + tig + 4]);
            }
            #pragma unroll
            for (int nf = 0; nf < 4; nf++) {
                int r = wn + nf * 8 + g;
                uint32_t bH0 = __float_as_uint(WsH[r][kb + tig]);
                uint32_t bH1 = __float_as_uint(WsH[r][kb + tig + 4]);
                uint32_t bL0 = __float_as_uint(WsL[r][kb + tig]);
                uint32_t bL1 = __float_as_uint(WsL[r][kb + tig + 4]);
                #pragma unroll
                for (int mf = 0; mf < 4; mf++) {
                    mma_tf32(c[mf][nf], aL[mf][0], aL[mf][1], aL[mf][2], aL[mf][3], bH0, bH1);
                    mma_tf32(c[mf][nf], aH[mf][0], aH[mf][1], aH[mf][2], aH[mf][3], bL0, bL1);
                    mma_tf32(c[mf][nf], aH[mf][0], aH[mf][1], aH[mf][2], aH[mf][3], bH0, bH1);
                }
            }
        }
        __syncthreads();
    }

    #pragma unroll
    for (int mf = 0; mf < 4; mf++) {
        #pragma unroll
        for (int nf = 0; nf < 4; nf++) {
            int mbase = m0 + wm + mf * 16 + g;
            int nbase = n0 + wn + nf * 8 + tig * 2;
            #pragma unroll
            for (int i = 0; i < 2; i++) {
                #pragma unroll
                for (int j = 0; j < 2; j++) {
                    int m = mbase + i * 8;
                    int n = nbase + j;
                    float v = c[mf][nf][i * 2 + j];
                    if (bias) v += bias[(long)z * bB + n];
                    if (resid) v += resid[(long)m * N + n];
                    if (act) v = fmaxf(v, 0.0f);
                    C[(long)m * N + n] = v;
                }
            }
        }
    }
}

// ---------------- RoPE in-place on q,k of g_qkv ----------------
__global__ void rope_kernel() {
    int n = blockIdx.x;
    int tid = threadIdx.x;  // 512
    int which = tid >> 8;
    int rem = tid & 255;
    int h = rem >> 5, j = rem & 31;
    int t = n % T;
    float div = expf(-(float)j * (9.210340371976184f / 32.0f));
    float ang = (float)t * div;
    float c = cosf(ang), s = sinf(ang);
    float* p = g_qkv + (long)n * 3 * E + which * E + h * DH;
    float a1 = p[j], a2 = p[j + HALF];
    p[j] = a1 * c - a2 * s;
    p[j + HALF] = a2 * c + a1 * s;
}

// ---------------- tiled flash attention ----------------
// CTA: 256 threads, one (b,h) and 128 queries. 2 lanes per query (each owns a
// 32-dim half). K/V tiles of 64 keys staged in smem. Output written in the
// reference's permuted layout: row t' = h*128 + t/8, channel e' = (t%8)*64 + d.
#define KT 64
__global__ void __launch_bounds__(256, 2) attn_tile_kernel() {
    int bidx = blockIdx.x;                  // b*64 + h*8 + qb
    int qb = bidx & 7;
    int h = (bidx >> 3) & 7;
    int b = bidx >> 6;
    int tid = threadIdx.x;
    int warp = tid >> 5, lane = tid & 31;
    int qi = warp * 16 + (lane >> 1);       // 0..127
    int t = qb * 128 + qi;
    int half = lane & 1;
    int n = b * T + t;
    __shared__ float Ks[KT][68];
    __shared__ float Vs[KT][68];
    float q[32];
    const float* qr = g_qkv + (long)n * 3 * E + h * DH + half * 32;
    #pragma unroll
    for (int j = 0; j < 32; j += 4) {
        float4 v = *(const float4*)(qr + j);
        q[j] = v.x * 0.125f; q[j + 1] = v.y * 0.125f;
        q[j + 2] = v.z * 0.125f; q[j + 3] = v.w * 0.125f;
    }
    float m = -INFINITY, lsum = 0.0f, acc[32];
    #pragma unroll
    for (int j = 0; j < 32; j++) acc[j] = 0.0f;
    const float* kvbase = g_qkv + (long)b * T * 3 * E + h * DH;
    for (int s0 = 0; s0 < T; s0 += KT) {
        #pragma unroll
        for (int i = 0; i < 4; i++) {
            int f = tid + 256 * i;           // 0..1023 float4 slots
            int r = f >> 4, c4 = (f & 15) * 4;
            const float* krow = kvbase + (long)(s0 + r) * 3 * E + E;
            *(float4*)&Ks[r][c4] = *(const float4*)(krow + c4);
            *(float4*)&Vs[r][c4] = *(const float4*)(krow + E + c4);
        }
        __syncthreads();
        #pragma unroll 2
        for (int s = 0; s < KT; s++) {
            const float* kr = &Ks[s][half * 32];
            float p = 0.0f;
            #pragma unroll
            for (int j = 0; j < 32; j += 4) {
                float4 kv = *(const float4*)(kr + j);
                p += q[j] * kv.x + q[j + 1] * kv.y + q[j + 2] * kv.z + q[j + 3] * kv.w;
            }
            p += __shfl_xor_sync(~0u, p, 1);
            float mn = fmaxf(m, p);
            float corr = __expf(m - mn);
            float w = __expf(p - mn);
            lsum = lsum * corr + w;
            m = mn;
            const float* vr = &Vs[s][half * 32];
            #pragma unroll
            for (int j = 0; j < 32; j += 4) {
                float4 vv = *(const float4*)(vr + j);
                acc[j]     = acc[j]     * corr + w * vv.x;
                acc[j + 1] = acc[j + 1] * corr + w * vv.y;
                acc[j + 2] = acc[j + 2] * corr + w * vv.z;
                acc[j + 3] = acc[j + 3] * corr + w * vv.w;
            }
        }
        __syncthreads();
    }
    float inv = 1.0f / lsum;
    int tp = h * 128 + (t >> 3);
    int ep = (t & 7) * 64 + half * 32;
    float* orow = g_att + ((long)b * T + tp) * E + ep;
    #pragma unroll
    for (int j = 0; j < 32; j++) orow[j] = acc[j] * inv;
}

// ---------------- router: warp per token, top-2 + gates ----------------
__global__ void router_kernel(const float* __restrict__ rw, const float* __restrict__ rb,
                              const float* __restrict__ nw, const float* __restrict__ nb,
                              const float* __restrict__ rn) {
    int gw = (blockIdx.x * blockDim.x + threadIdx.x) >> 5;
    int lane = threadIdx.x & 31;
    if (gw >= NTOK) return;
    const float* h = g_h + (long)gw * E;
    float hr[16];
    #pragma unroll
    for (int j = 0; j < 16; j++) hr[j] = h[lane + 32 * j];
    float lg[X], ng[X];
    #pragma unroll
    for (int e = 0; e < X; e++) {
        float a = 0, bn = 0;
        const float* wr = rw + (long)e * E;
        const float* wn = nw + (long)e * E;
        #pragma unroll
        for (int j = 0; j < 16; j++) {
            a += hr[j] * wr[lane + 32 * j];
            bn += hr[j] * wn[lane + 32 * j];
        }
        #pragma unroll
        for (int o = 16; o; o >>= 1) {
            a += __shfl_xor_sync(~0u, a, o);
            bn += __shfl_xor_sync(~0u, bn, o);
        }
        lg[e] = a;
        ng[e] = bn;
    }
    if (lane == 0) {
        float noisy[X];
        #pragma unroll
        for (int e = 0; e < X; e++) {
            float lo = lg[e] + rb[e];
            float nl = ng[e] + nb[e];
            float sp = nl > 0.0f ? nl + log1pf(expf(-nl)) : log1pf(expf(nl));
            noisy[e] = lo + rn[(long)gw * X + e] * sp;
        }
        int b1 = 0; float v1 = noisy[0];
        #pragma unroll
        for (int e = 1; e < X; e++) if (noisy[e] > v1) { v1 = noisy[e]; b1 = e; }
        int b2 = -1; float v2 = -INFINITY;
        #pragma unroll
        for (int e = 0; e < X; e++) if (e != b1 && noisy[e] > v2) { v2 = noisy[e]; b2 = e; }
        float zz = expf(v2 - v1);
        float p1 = 1.0f / (1.0f + zz);
        float p2 = zz / (1.0f + zz);
        g_topi[gw * 2] = b1; g_topi[gw * 2 + 1] = b2;
        g_gatev[gw * 2] = p1; g_gatev[gw * 2 + 1] = p2;
    }
}

// ---------------- dispatch: ordered compaction per expert ----------------
__global__ void dispatch_kernel() {
    int e = blockIdx.x;
    int tid = threadIdx.x, lane = tid & 31, wid = tid >> 5;
    __shared__ int wsum[8];
    __shared__ int sbase;
    if (tid == 0) sbase = 0;
    __syncthreads();
    for (int c = 0; c < NTOK; c += 256) {
        int n = c + tid;
        int k = -1;
        if (g_topi[n * 2] == e) k = 0;
        else if (g_topi[n * 2 + 1] == e) k = 1;
        unsigned bal = __ballot_sync(~0u, k >= 0);
        if (lane == 0) wsum[wid] = __popc(bal);
        __syncthreads();
        int pre = 0, total = 0;
        #pragma unroll
        for (int w8 = 0; w8 < 8; w8++) {
            total += wsum[w8];
            if (w8 < wid) pre += wsum[w8];
        }
        if (k >= 0) {
            int pos = sbase + pre + __popc(bal & ((1u << lane) - 1));
            if (pos < CAP) {
                g_idx[e * CAP + pos] = n;
                g_gate[e * CAP + pos] = g_gatev[n * 2 + k];
                g_slot[n * 2 + k] = e * CAP + pos;
            } else {
                g_slot[n * 2 + k] = -1;
            }
        }
        __syncthreads();
        if (tid == 0) sbase += total;
        __syncthreads();
    }
    if (tid == 0) g_cnt[e] = sbase < CAP ? sbase : CAP;
}

// ---------------- gather expert inputs ----------------
__global__ void gather_kernel() {
    int r = blockIdx.x;
    int e = r / CAP, s = r % CAP;
    float4* dst = (float4*)(g_ein + (long)r * E);
    int i = threadIdx.x;
    if (s < g_cnt[e]) {
        const float4* src = (const float4*)(g_h + (long)g_idx[r] * E);
        dst[i] = src[i];
    } else {
        float4 zf = {0, 0, 0, 0};
        dst[i] = zf;
    }
}

// ---------------- combine ----------------
__global__ void combine_kernel() {
    int n = blockIdx.x;
    int i = threadIdx.x;
    float4* xr = (float4*)(g_x + (long)n * E);
    float4 v = xr[i];
    #pragma unroll
    for (int k = 0; k < 2; k++) {
        int s = g_slot[n * 2 + k];
        if (s >= 0) {
            float g = g_gate[s];
            float4 eo = ((const float4*)(g_eout + (long)s * E))[i];
            v.x += g * eo.x; v.y += g * eo.y; v.z += g * eo.z; v.w += g * eo.w;
        }
    }
    xr[i] = v;
}

// ---------------- attention pooling ----------------
__global__ void pool_kernel(const float* __restrict__ pq) {
    int b = blockIdx.x;
    int tid = threadIdx.x, lane = tid & 31, wid = tid >> 5;
    __shared__ float s[T];
    __shared__ float red[8];
    const float* hb = g_h + (long)b * T * E;
    for (int t = wid; t < T; t += 8) {
        float acc = 0;
        const float* row = hb + (long)t * E;
        for (int i = lane; i < E; i += 32) acc += pq[i] * row[i];
        #pragma unroll
        for (int o = 16; o; o >>= 1) acc += __shfl_xor_sync(~0u, acc, o);
        if (lane == 0) s[t] = acc * (1.0f / 22.627416997969522f);
    }
    __syncthreads();
    float m = -INFINITY;
    for (int t = tid; t < T; t += 256) m = fmaxf(m, s[t]);
    #pragma unroll
    for (int o = 16; o; o >>= 1) m = fmaxf(m, __shfl_xor_sync(~0u, m, o));
    if (lane == 0) red[wid] = m;
    __syncthreads();
    float mm = red[0];
    #pragma unroll
    for (int w8 = 1; w8 < 8; w8++) mm = fmaxf(mm, red[w8]);
    float sum = 0;
    for (int t = tid; t < T; t += 256) {
        float e2 = expf(s[t] - mm);
        s[t] = e2;
        sum += e2;
    }
    #pragma unroll
    for (int o = 16; o; o >>= 1) sum += __shfl_xor_sync(~0u, sum, o);
    __syncthreads();
    if (lane == 0) red[wid] = sum;
    __syncthreads();
    float tot = 0;
    #pragma unroll
    for (int w8 = 0; w8 < 8; w8++) tot += red[w8];
    float inv = 1.0f / tot;
    for (int e0 = tid; e0 < E; e0 += 256) {
        float acc = 0;
        for (int t = 0; t < T; t++) acc += s[t] * hb[(long)t * E + e0];
        g_pool[(long)b * E + e0] = acc * inv;
    }
}

// ---------------- warp-per-output GEMV ----------------
__global__ void gemv_warp(const float* __restrict__ A, const float* __restrict__ W,
                          const float* __restrict__ bias, float* __restrict__ C,
                          int M, int N, int Kd) {
    int gw = (blockIdx.x * blockDim.x + threadIdx.x) >> 5;
    int lane = threadIdx.x & 31;
    if (gw >= M * N) return;
    int m = gw / N, n = gw % N;
    const float* a = A + (long)m * Kd;
    const float* w = W + (long)n * Kd;
    float acc = 0;
    for (int i = lane; i < Kd; i += 32) acc += a[i] * w[i];
    #pragma unroll
    for (int o = 16; o; o >>= 1) acc += __shfl_xor_sync(~0u, acc, o);
    if (lane == 0) C[(long)m * N + n] = acc + (bias ? bias[n] : 0.0f);
}

// ---------------- final head ----------------
__global__ void head2_kernel(const float* __restrict__ w2, const float* __restrict__ b2,
                             float* __restrict__ out) {
    int b = blockIdx.x;
    int lane = threadIdx.x;
    float acc = 0;
    for (int i = lane; i < HID; i += 32) acc += fmaxf(g_o1[(long)b * HID + i], 0.0f) * w2[i];
    #pragma unroll
    for (int o = 16; o; o >>= 1) acc += __shfl_xor_sync(~0u, acc, o);
    if (lane == 0) out[b] = acc + b2[0];
}

// ---------------- host ----------------
extern "C" void kernel_launch(void* const* d_in, const int* in_sizes, int n_in,
                              void* d_out, int out_size) {
    const float* tok_emb = (const float*)d_in[0];
    const float* pos_emb = (const float*)d_in[1];
    const float* ln1_w = (const float*)d_in[2];
    const float* ln1_b = (const float*)d_in[3];
    const float* ln2_w = (const float*)d_in[4];
    const float* ln2_b = (const float*)d_in[5];
    const float* qkv_w = (const float*)d_in[6];
    const float* out_w = (const float*)d_in[7];
    const float* route_w = (const float*)d_in[8];
    const float* route_b = (const float*)d_in[9];
    const float* noise_w = (const float*)d_in[10];
    const float* noise_b = (const float*)d_in[11];
    const float* exp_w1 = (const float*)d_in[12];
    const float* exp_b1 = (const float*)d_in[13];
    const float* exp_w2 = (const float*)d_in[14];
    const float* exp_b2 = (const float*)d_in[15];
    const float* lnf_w = (const float*)d_in[16];
    const float* lnf_b = (const float*)d_in[17];
    const float* pool_q = (const float*)d_in[18];
    const float* pool_w = (const float*)d_in[19];
    const float* pool_b = (const float*)d_in[20];
    const float* head_w1 = (const float*)d_in[21];
    const float* head_b1 = (const float*)d_in[22];
    const float* head_w2 = (const float*)d_in[23];
    const float* head_b2 = (const float*)d_in[24];
    const int* ids = (const int*)d_in[25];
    const float* rnoise = (const float*)d_in[26];
    float* out = (float*)d_out;

    float *px, *ph, *pqkv, *patt, *pein, *pehid, *peout, *ppool, *phv, *po1;
    cudaGetSymbolAddress((void**)&px, g_x);
    cudaGetSymbolAddress((void**)&ph, g_h);
    cudaGetSymbolAddress((void**)&pqkv, g_qkv);
    cudaGetSymbolAddress((void**)&patt, g_att);
    cudaGetSymbolAddress((void**)&pein, g_ein);
    cudaGetSymbolAddress((void**)&pehid, g_ehid);
    cudaGetSymbolAddress((void**)&peout, g_eout);
    cudaGetSymbolAddress((void**)&ppool, g_pool);
    cudaGetSymbolAddress((void**)&phv, g_hv);
    cudaGetSymbolAddress((void**)&po1, g_o1);

    embed_kernel<<<NTOK, 128>>>(tok_emb, pos_emb, ids);

    for (int l = 0; l < NL; l++) {
        ln_kernel<<<NTOK, 256>>>(px, ln1_w + l * E, ln1_b + l * E, ph);
        {
            dim3 g(3 * E / 128, NTOK / 128, 1);
            gemm_tf32<<<g, 256>>>(ph, qkv_w + (long)l * 3 * E * E, nullptr, nullptr,
                                  pqkv, NTOK, 3 * E, E, 0, 0, 0, 0, 0);
        }
        rope_kernel<<<NTOK, 512>>>();
        attn_tile_kernel<<<BB * HN * (T / 128), 256>>>();
        {
            dim3 g(E / 128, NTOK / 128, 1);
            gemm_tf32<<<g, 256>>>(patt, out_w + (long)l * E * E, nullptr, px,
                                  px, NTOK, E, E, 0, 0, 0, 0, 0);
        }
        ln_kernel<<<NTOK, 256>>>(px, ln2_w + l * E, ln2_b + l * E, ph);
        router_kernel<<<NTOK / 8, 256>>>(route_w + (long)l * X * E, route_b + l * X,
                                         noise_w + (long)l * X * E, noise_b + l * X,
                                         rnoise + (long)l * NTOK * X);
        dispatch_kernel<<<X, 256>>>();
        gather_kernel<<<X * CAP, 128>>>();
        {
            dim3 g1(H4 / 128, CAP / 128, X);
            gemm_tf32<<<g1, 256>>>(pein, exp_w1 + (long)l * X * H4 * E,
                                   exp_b1 + (long)l * X * H4, nullptr, pehid,
                                   CAP, H4, E, CAP * E, H4 * E, H4, CAP * H4, 1);
            dim3 g2(E / 128, CAP / 128, X);
            gemm_tf32<<<g2, 256>>>(pehid, exp_w2 + (long)l * X * E * H4,
                                   exp_b2 + (long)l * X * E, nullptr, peout,
                                   CAP, E, H4, CAP * H4, E * H4, E, CAP * E, 0);
        }
        combine_kernel<<<NTOK, 128>>>();
    }

    ln_kernel<<<NTOK, 256>>>(px, lnf_w, lnf_b, ph);
    pool_kernel<<<BB, 256>>>(pool_q);
    gemv_warp<<<(BB * HIGH * 32) / 256, 256>>>(ppool, pool_w, pool_b, phv, BB, HIGH, E);
    gemv_warp<<<(BB * HID * 32) / 256, 256>>>(phv, head_w1, head_b1, po1, BB, HID, HIGH);
    head2_kernel<<<BB, 32>>>(head_w2, head_b2, out);
}

// round 9
// speedup vs baseline: 1.9849x; 1.0819x over previous
#include <cuda_runtime.h>
#include <math.h>
#include <stdint.h>

#define E 512
#define T 1024
#define BB 8
#define HN 8
#define DH 64
#define HALF 32
#define NL 4
#define X 8
#define TOPK 2
#define CAP 2048
#define H4 2048
#define NTOK 8192
#define HIGH 32000
#define HID 1024

// ---------------- scratch (device globals; no allocation allowed) ----------------
__device__ float g_x[NTOK * E];
__device__ float g_h[NTOK * E];
__device__ float g_qkv[NTOK * 3 * E];
__device__ float g_att[NTOK * E];
__device__ int   g_topi[NTOK * TOPK];
__device__ float g_gatev[NTOK * TOPK];
__device__ int   g_idx[X * CAP];
__device__ float g_gate[X * CAP];
__device__ int   g_slot[NTOK * TOPK];
__device__ int   g_cnt[X];
__device__ float g_ein[X * CAP * E];
__device__ float g_ehid[(long)X * CAP * H4];
__device__ float g_eout[X * CAP * E];
__device__ float g_pool[BB * E];
__device__ float g_hv[BB * HIGH];
__device__ float g_o1[BB * HID];

// ---------------- embed ----------------
__global__ void embed_kernel(const float* __restrict__ tok, const float* __restrict__ pos,
                             const int* __restrict__ ids) {
    int n = blockIdx.x;
    int t = n % T;
    int id = ids[n];
    const float4* te = (const float4*)(tok + (long)id * E);
    const float4* pe = (const float4*)(pos + (long)t * E);
    float4* xr = (float4*)(g_x + (long)n * E);
    int i = threadIdx.x;
    float4 a = te[i], b = pe[i];
    a.x += b.x; a.y += b.y; a.z += b.z; a.w += b.w;
    xr[i] = a;
}

// ---------------- layernorm ----------------
__global__ void ln_kernel(const float* __restrict__ in, const float* __restrict__ w,
                          const float* __restrict__ b, float* __restrict__ out) {
    int n = blockIdx.x;
    int tid = threadIdx.x, lane = tid & 31, wid = tid >> 5;
    __shared__ float red[8];
    const float* r = in + (long)n * E;
    float v0 = r[tid], v1 = r[tid + 256];
    float s = v0 + v1;
    #pragma unroll
    for (int o = 16; o; o >>= 1) s += __shfl_xor_sync(~0u, s, o);
    if (lane == 0) red[wid] = s;
    __syncthreads();
    float tot = 0;
    #pragma unroll
    for (int w8 = 0; w8 < 8; w8++) tot += red[w8];
    float mean = tot * (1.0f / E);
    float d0 = v0 - mean, d1 = v1 - mean;
    float sq = d0 * d0 + d1 * d1;
    __syncthreads();
    #pragma unroll
    for (int o = 16; o; o >>= 1) sq += __shfl_xor_sync(~0u, sq, o);
    if (lane == 0) red[wid] = sq;
    __syncthreads();
    float tv = 0;
    #pragma unroll
    for (int w8 = 0; w8 < 8; w8++) tv += red[w8];
    float inv = rsqrtf(tv * (1.0f / E) + 1e-5f);
    out[(long)n * E + tid] = d0 * inv * w[tid] + b[tid];
    out[(long)n * E + tid + 256] = d1 * inv * w[tid + 256] + b[tid + 256];
}

// ---------------- tf32 helpers ----------------
__device__ __forceinline__ float tf32r(float x) {
    uint32_t u;
    asm("cvt.rna.tf32.f32 %0, %1;" : "=r"(u) : "f"(x));
    return __uint_as_float(u);
}

__device__ __forceinline__ void mma_tf32(float c[4], uint32_t a0, uint32_t a1,
                                         uint32_t a2, uint32_t a3,
                                         uint32_t b0, uint32_t b1) {
    asm volatile(
        "mma.sync.aligned.m16n8k8.row.col.f32.tf32.tf32.f32 "
        "{%0,%1,%2,%3}, {%4,%5,%6,%7}, {%8,%9}, {%0,%1,%2,%3};"
        : "+f"(c[0]), "+f"(c[1]), "+f"(c[2]), "+f"(c[3])
        : "r"(a0), "r"(a1), "r"(a2), "r"(a3), "r"(b0), "r"(b1));
}

__device__ __forceinline__ void cp16(void* dst, const void* src) {
    uint32_t d = (uint32_t)__cvta_generic_to_shared(dst);
    asm volatile("cp.async.ca.shared.global [%0], [%1], 16;" :: "r"(d), "l"(src));
}

// ---------------- 3xTF32 tensor-core GEMM, cp.async 2-stage pipeline ----------------
// C = act(A @ W^T + bias [+resid]); A [M,Kd], W [N,Kd] row-major.
// 128x128x16 tiles, 256 threads, warp grid 2(M)x4(N), warp tile 64x32.
// Raw fp32 staged in smem; tf32 hi/lo split done at fragment-load time.
#define SKP 20
__global__ void __launch_bounds__(256, 2)
gemm_tf32(const float* __restrict__ A, const float* __restrict__ W,
          const float* __restrict__ bias, const float* __restrict__ resid,
          float* __restrict__ C, int M, int N, int Kd,
          int aB, int wB, int bB, int cB, int act) {
    int z = blockIdx.z;
    A += (long)z * aB;
    W += (long)z * wB;
    C += (long)z * cB;
    __shared__ float As[2][128][SKP];
    __shared__ float Ws[2][128][SKP];
    int tid = threadIdx.x;
    int lane = tid & 31, w = tid >> 5;
    int g = lane >> 2, tig = lane & 3;
    int wm = (w >> 2) * 64, wn = (w & 3) * 32;
    int m0 = blockIdx.y * 128, n0 = blockIdx.x * 128;
    int lrow = tid >> 2, lkc = (tid & 3) * 4;   // 0..63 rows, this thread also does lrow+64
    float c[4][4][4] = {};

    const float* Ab = A + (long)(m0 + lrow) * Kd + lkc;
    const float* Ab2 = A + (long)(m0 + lrow + 64) * Kd + lkc;
    const float* Wb = W + (long)(n0 + lrow) * Kd + lkc;
    const float* Wb2 = W + (long)(n0 + lrow + 64) * Kd + lkc;

    // prologue: stage 0
    cp16(&As[0][lrow][lkc], Ab);
    cp16(&As[0][lrow + 64][lkc], Ab2);
    cp16(&Ws[0][lrow][lkc], Wb);
    cp16(&Ws[0][lrow + 64][lkc], Wb2);
    asm volatile("cp.async.commit_group;");

    int nk = Kd >> 4;
    for (int kt = 0; kt < nk; kt++) {
        if (kt + 1 < nk) {
            int s = (kt + 1) & 1;
            int ko = (kt + 1) << 4;
            cp16(&As[s][lrow][lkc], Ab + ko);
            cp16(&As[s][lrow + 64][lkc], Ab2 + ko);
            cp16(&Ws[s][lrow][lkc], Wb + ko);
            cp16(&Ws[s][lrow + 64][lkc], Wb2 + ko);
            asm volatile("cp.async.commit_group;");
            asm volatile("cp.async.wait_group 1;");
        } else {
            asm volatile("cp.async.wait_group 0;");
        }
        __syncthreads();
        int st = kt & 1;
        #pragma unroll
        for (int ks = 0; ks < 2; ks++) {
            int kb = ks * 8;
            uint32_t bH[4][2], bL[4][2];
            #pragma unroll
            for (int nf = 0; nf < 4; nf++) {
                int r = wn + nf * 8 + g;
                float b0 = Ws[st][r][kb + tig];
                float b1 = Ws[st][r][kb + tig + 4];
                float h0 = tf32r(b0), h1 = tf32r(b1);
                bH[nf][0] = __float_as_uint(h0);
                bH[nf][1] = __float_as_uint(h1);
                bL[nf][0] = __float_as_uint(tf32r(b0 - h0));
                bL[nf][1] = __float_as_uint(tf32r(b1 - h1));
            }
            #pragma unroll
            for (int mf = 0; mf < 4; mf++) {
                int r = wm + mf * 16 + g;
                float a0 = As[st][r][kb + tig];
                float a1 = As[st][r + 8][kb + tig];
                float a2 = As[st][r][kb + tig + 4];
                float a3 = As[st][r + 8][kb + tig + 4];
                float h0 = tf32r(a0), h1 = tf32r(a1), h2 = tf32r(a2), h3 = tf32r(a3);
                uint32_t aH0 = __float_as_uint(h0), aH1 = __float_as_uint(h1);
                uint32_t aH2 = __float_as_uint(h2), aH3 = __float_as_uint(h3);
                uint32_t aL0 = __float_as_uint(tf32r(a0 - h0));
                uint32_t aL1 = __float_as_uint(tf32r(a1 - h1));
                uint32_t aL2 = __float_as_uint(tf32r(a2 - h2));
                uint32_t aL3 = __float_as_uint(tf32r(a3 - h3));
                #pragma unroll
                for (int nf = 0; nf < 4; nf++) {
                    mma_tf32(c[mf][nf], aL0, aL1, aL2, aL3, bH[nf][0], bH[nf][1]);
                    mma_tf32(c[mf][nf], aH0, aH1, aH2, aH3, bL[nf][0], bL[nf][1]);
                    mma_tf32(c[mf][nf], aH0, aH1, aH2, aH3, bH[nf][0], bH[nf][1]);
                }
            }
        }
        __syncthreads();
    }

    #pragma unroll
    for (int mf = 0; mf < 4; mf++) {
        #pragma unroll
        for (int nf = 0; nf < 4; nf++) {
            int mbase = m0 + wm + mf * 16 + g;
            int nbase = n0 + wn + nf * 8 + tig * 2;
            #pragma unroll
            for (int i = 0; i < 2; i++) {
                #pragma unroll
                for (int j = 0; j < 2; j++) {
                    int m = mbase + i * 8;
                    int n = nbase + j;
                    float v = c[mf][nf][i * 2 + j];
                    if (bias) v += bias[(long)z * bB + n];
                    if (resid) v += resid[(long)m * N + n];
                    if (act) v = fmaxf(v, 0.0f);
                    C[(long)m * N + n] = v;
                }
            }
        }
    }
}

// ---------------- RoPE in-place on q,k of g_qkv ----------------
__global__ void rope_kernel() {
    int n = blockIdx.x;
    int tid = threadIdx.x;  // 512
    int which = tid >> 8;
    int rem = tid & 255;
    int h = rem >> 5, j = rem & 31;
    int t = n % T;
    float div = expf(-(float)j * (9.210340371976184f / 32.0f));
    float ang = (float)t * div;
    float c = cosf(ang), s = sinf(ang);
    float* p = g_qkv + (long)n * 3 * E + which * E + h * DH;
    float a1 = p[j], a2 = p[j + HALF];
    p[j] = a1 * c - a2 * s;
    p[j + HALF] = a2 * c + a1 * s;
}

// ---------------- tiled flash attention ----------------
// CTA: 256 threads, one (b,h) and 128 queries; 2 lanes per query (32-dim halves).
// K/V tiles of 64 keys in smem. Output in the reference's permuted layout:
// row t' = h*128 + t/8, channel e' = (t%8)*64 + d.
#define KT 64
__global__ void __launch_bounds__(256, 2) attn_tile_kernel() {
    int bidx = blockIdx.x;                  // b*64 + h*8 + qb
    int qb = bidx & 7;
    int h = (bidx >> 3) & 7;
    int b = bidx >> 6;
    int tid = threadIdx.x;
    int warp = tid >> 5, lane = tid & 31;
    int qi = warp * 16 + (lane >> 1);
    int t = qb * 128 + qi;
    int half = lane & 1;
    int n = b * T + t;
    __shared__ float Ks[KT][68];
    __shared__ float Vs[KT][68];
    float q[32];
    const float* qr = g_qkv + (long)n * 3 * E + h * DH + half * 32;
    #pragma unroll
    for (int j = 0; j < 32; j += 4) {
        float4 v = *(const float4*)(qr + j);
        q[j] = v.x * 0.125f; q[j + 1] = v.y * 0.125f;
        q[j + 2] = v.z * 0.125f; q[j + 3] = v.w * 0.125f;
    }
    float m = -INFINITY, lsum = 0.0f, acc[32];
    #pragma unroll
    for (int j = 0; j < 32; j++) acc[j] = 0.0f;
    const float* kvbase = g_qkv + (long)b * T * 3 * E + h * DH;
    for (int s0 = 0; s0 < T; s0 += KT) {
        #pragma unroll
        for (int i = 0; i < 4; i++) {
            int f = tid + 256 * i;
            int r = f >> 4, c4 = (f & 15) * 4;
            const float* krow = kvbase + (long)(s0 + r) * 3 * E + E;
            *(float4*)&Ks[r][c4] = *(const float4*)(krow + c4);
            *(float4*)&Vs[r][c4] = *(const float4*)(krow + E + c4);
        }
        __syncthreads();
        #pragma unroll 2
        for (int s = 0; s < KT; s++) {
            const float* kr = &Ks[s][half * 32];
            float p = 0.0f;
            #pragma unroll
            for (int j = 0; j < 32; j += 4) {
                float4 kv = *(const float4*)(kr + j);
                p += q[j] * kv.x + q[j + 1] * kv.y + q[j + 2] * kv.z + q[j + 3] * kv.w;
            }
            p += __shfl_xor_sync(~0u, p, 1);
            float mn = fmaxf(m, p);
            float corr = __expf(m - mn);
            float w = __expf(p - mn);
            lsum = lsum * corr + w;
            m = mn;
            const float* vr = &Vs[s][half * 32];
            #pragma unroll
            for (int j = 0; j < 32; j += 4) {
                float4 vv = *(const float4*)(vr + j);
                acc[j]     = acc[j]     * corr + w * vv.x;
                acc[j + 1] = acc[j + 1] * corr + w * vv.y;
                acc[j + 2] = acc[j + 2] * corr + w * vv.z;
                acc[j + 3] = acc[j + 3] * corr + w * vv.w;
            }
        }
        __syncthreads();
    }
    float inv = 1.0f / lsum;
    int tp = h * 128 + (t >> 3);
    int ep = (t & 7) * 64 + half * 32;
    float* orow = g_att + ((long)b * T + tp) * E + ep;
    #pragma unroll
    for (int j = 0; j < 32; j += 4) {
        float4 ov;
        ov.x = acc[j] * inv; ov.y = acc[j + 1] * inv;
        ov.z = acc[j + 2] * inv; ov.w = acc[j + 3] * inv;
        *(float4*)(orow + j) = ov;
    }
}

// ---------------- router: warp per token, top-2 + gates ----------------
__global__ void router_kernel(const float* __restrict__ rw, const float* __restrict__ rb,
                              const float* __restrict__ nw, const float* __restrict__ nb,
                              const float* __restrict__ rn) {
    int gw = (blockIdx.x * blockDim.x + threadIdx.x) >> 5;
    int lane = threadIdx.x & 31;
    if (gw >= NTOK) return;
    const float* h = g_h + (long)gw * E;
    float hr[16];
    #pragma unroll
    for (int j = 0; j < 16; j++) hr[j] = h[lane + 32 * j];
    float lg[X], ng[X];
    #pragma unroll
    for (int e = 0; e < X; e++) {
        float a = 0, bn = 0;
        const float* wr = rw + (long)e * E;
        const float* wn = nw + (long)e * E;
        #pragma unroll
        for (int j = 0; j < 16; j++) {
            a += hr[j] * wr[lane + 32 * j];
            bn += hr[j] * wn[lane + 32 * j];
        }
        #pragma unroll
        for (int o = 16; o; o >>= 1) {
            a += __shfl_xor_sync(~0u, a, o);
            bn += __shfl_xor_sync(~0u, bn, o);
        }
        lg[e] = a;
        ng[e] = bn;
    }
    if (lane == 0) {
        float noisy[X];
        #pragma unroll
        for (int e = 0; e < X; e++) {
            float lo = lg[e] + rb[e];
            float nl = ng[e] + nb[e];
            float sp = nl > 0.0f ? nl + log1pf(expf(-nl)) : log1pf(expf(nl));
            noisy[e] = lo + rn[(long)gw * X + e] * sp;
        }
        int b1 = 0; float v1 = noisy[0];
        #pragma unroll
        for (int e = 1; e < X; e++) if (noisy[e] > v1) { v1 = noisy[e]; b1 = e; }
        int b2 = -1; float v2 = -INFINITY;
        #pragma unroll
        for (int e = 0; e < X; e++) if (e != b1 && noisy[e] > v2) { v2 = noisy[e]; b2 = e; }
        float zz = expf(v2 - v1);
        float p1 = 1.0f / (1.0f + zz);
        float p2 = zz / (1.0f + zz);
        g_topi[gw * 2] = b1; g_topi[gw * 2 + 1] = b2;
        g_gatev[gw * 2] = p1; g_gatev[gw * 2 + 1] = p2;
    }
}

// ---------------- dispatch: ordered compaction per expert ----------------
__global__ void dispatch_kernel() {
    int e = blockIdx.x;
    int tid = threadIdx.x, lane = tid & 31, wid = tid >> 5;
    __shared__ int wsum[8];
    __shared__ int sbase;
    if (tid == 0) sbase = 0;
    __syncthreads();
    for (int c = 0; c < NTOK; c += 256) {
        int n = c + tid;
        int k = -1;
        if (g_topi[n * 2] == e) k = 0;
        else if (g_topi[n * 2 + 1] == e) k = 1;
        unsigned bal = __ballot_sync(~0u, k >= 0);
        if (lane == 0) wsum[wid] = __popc(bal);
        __syncthreads();
        int pre = 0, total = 0;
        #pragma unroll
        for (int w8 = 0; w8 < 8; w8++) {
            total += wsum[w8];
            if (w8 < wid) pre += wsum[w8];
        }
        if (k >= 0) {
            int pos = sbase + pre + __popc(bal & ((1u << lane) - 1));
            if (pos < CAP) {
                g_idx[e * CAP + pos] = n;
                g_gate[e * CAP + pos] = g_gatev[n * 2 + k];
                g_slot[n * 2 + k] = e * CAP + pos;
            } else {
                g_slot[n * 2 + k] = -1;
            }
        }
        __syncthreads();
        if (tid == 0) sbase += total;
        __syncthreads();
    }
    if (tid == 0) g_cnt[e] = sbase < CAP ? sbase : CAP;
}

// ---------------- gather expert inputs ----------------
__global__ void gather_kernel() {
    int r = blockIdx.x;
    int e = r / CAP, s = r % CAP;
    float4* dst = (float4*)(g_ein + (long)r * E);
    int i = threadIdx.x;
    if (s < g_cnt[e]) {
        const float4* src = (const float4*)(g_h + (long)g_idx[r] * E);
        dst[i] = src[i];
    } else {
        float4 zf = {0, 0, 0, 0};
        dst[i] = zf;
    }
}

// ---------------- combine ----------------
__global__ void combine_kernel() {
    int n = blockIdx.x;
    int i = threadIdx.x;
    float4* xr = (float4*)(g_x + (long)n * E);
    float4 v = xr[i];
    #pragma unroll
    for (int k = 0; k < 2; k++) {
        int s = g_slot[n * 2 + k];
        if (s >= 0) {
            float g = g_gate[s];
            float4 eo = ((const float4*)(g_eout + (long)s * E))[i];
            v.x += g * eo.x; v.y += g * eo.y; v.z += g * eo.z; v.w += g * eo.w;
        }
    }
    xr[i] = v;
}

// ---------------- attention pooling ----------------
__global__ void pool_kernel(const float* __restrict__ pq) {
    int b = blockIdx.x;
    int tid = threadIdx.x, lane = tid & 31, wid = tid >> 5;
    __shared__ float s[T];
    __shared__ float red[8];
    const float* hb = g_h + (long)b * T * E;
    for (int t = wid; t < T; t += 8) {
        float acc = 0;
        const float* row = hb + (long)t * E;
        for (int i = lane; i < E; i += 32) acc += pq[i] * row[i];
        #pragma unroll
        for (int o = 16; o; o >>= 1) acc += __shfl_xor_sync(~0u, acc, o);
        if (lane == 0) s[t] = acc * (1.0f / 22.627416997969522f);
    }
    __syncthreads();
    float m = -INFINITY;
    for (int t = tid; t < T; t += 256) m = fmaxf(m, s[t]);
    #pragma unroll
    for (int o = 16; o; o >>= 1) m = fmaxf(m, __shfl_xor_sync(~0u, m, o));
    if (lane == 0) red[wid] = m;
    __syncthreads();
    float mm = red[0];
    #pragma unroll
    for (int w8 = 1; w8 < 8; w8++) mm = fmaxf(mm, red[w8]);
    float sum = 0;
    for (int t = tid; t < T; t += 256) {
        float e2 = expf(s[t] - mm);
        s[t] = e2;
        sum += e2;
    }
    #pragma unroll
    for (int o = 16; o; o >>= 1) sum += __shfl_xor_sync(~0u, sum, o);
    __syncthreads();
    if (lane == 0) red[wid] = sum;
    __syncthreads();
    float tot = 0;
    #pragma unroll
    for (int w8 = 0; w8 < 8; w8++) tot += red[w8];
    float inv = 1.0f / tot;
    for (int e0 = tid; e0 < E; e0 += 256) {
        float acc = 0;
        for (int t = 0; t < T; t++) acc += s[t] * hb[(long)t * E + e0];
        g_pool[(long)b * E + e0] = acc * inv;
    }
}

// ---------------- warp-per-output GEMV ----------------
__global__ void gemv_warp(const float* __restrict__ A, const float* __restrict__ W,
                          const float* __restrict__ bias, float* __restrict__ C,
                          int M, int N, int Kd) {
    int gw = (blockIdx.x * blockDim.x + threadIdx.x) >> 5;
    int lane = threadIdx.x & 31;
    if (gw >= M * N) return;
    int m = gw / N, n = gw % N;
    const float* a = A + (long)m * Kd;
    const float* w = W + (long)n * Kd;
    float acc = 0;
    for (int i = lane; i < Kd; i += 32) acc += a[i] * w[i];
    #pragma unroll
    for (int o = 16; o; o >>= 1) acc += __shfl_xor_sync(~0u, acc, o);
    if (lane == 0) C[(long)m * N + n] = acc + (bias ? bias[n] : 0.0f);
}

// ---------------- final head ----------------
__global__ void head2_kernel(const float* __restrict__ w2, const float* __restrict__ b2,
                             float* __restrict__ out) {
    int b = blockIdx.x;
    int lane = threadIdx.x;
    float acc = 0;
    for (int i = lane; i < HID; i += 32) acc += fmaxf(g_o1[(long)b * HID + i], 0.0f) * w2[i];
    #pragma unroll
    for (int o = 16; o; o >>= 1) acc += __shfl_xor_sync(~0u, acc, o);
    if (lane == 0) out[b] = acc + b2[0];
}

// ---------------- host ----------------
extern "C" void kernel_launch(void* const* d_in, const int* in_sizes, int n_in,
                              void* d_out, int out_size) {
    const float* tok_emb = (const float*)d_in[0];
    const float* pos_emb = (const float*)d_in[1];
    const float* ln1_w = (const float*)d_in[2];
    const float* ln1_b = (const float*)d_in[3];
    const float* ln2_w = (const float*)d_in[4];
    const float* ln2_b = (const float*)d_in[5];
    const float* qkv_w = (const float*)d_in[6];
    const float* out_w = (const float*)d_in[7];
    const float* route_w = (const float*)d_in[8];
    const float* route_b = (const float*)d_in[9];
    const float* noise_w = (const float*)d_in[10];
    const float* noise_b = (const float*)d_in[11];
    const float* exp_w1 = (const float*)d_in[12];
    const float* exp_b1 = (const float*)d_in[13];
    const float* exp_w2 = (const float*)d_in[14];
    const float* exp_b2 = (const float*)d_in[15];
    const float* lnf_w = (const float*)d_in[16];
    const float* lnf_b = (const float*)d_in[17];
    const float* pool_q = (const float*)d_in[18];
    const float* pool_w = (const float*)d_in[19];
    const float* pool_b = (const float*)d_in[20];
    const float* head_w1 = (const float*)d_in[21];
    const float* head_b1 = (const float*)d_in[22];
    const float* head_w2 = (const float*)d_in[23];
    const float* head_b2 = (const float*)d_in[24];
    const int* ids = (const int*)d_in[25];
    const float* rnoise = (const float*)d_in[26];
    float* out = (float*)d_out;

    float *px, *ph, *pqkv, *patt, *pein, *pehid, *peout, *ppool, *phv, *po1;
    cudaGetSymbolAddress((void**)&px, g_x);
    cudaGetSymbolAddress((void**)&ph, g_h);
    cudaGetSymbolAddress((void**)&pqkv, g_qkv);
    cudaGetSymbolAddress((void**)&patt, g_att);
    cudaGetSymbolAddress((void**)&pein, g_ein);
    cudaGetSymbolAddress((void**)&pehid, g_ehid);
    cudaGetSymbolAddress((void**)&peout, g_eout);
    cudaGetSymbolAddress((void**)&ppool, g_pool);
    cudaGetSymbolAddress((void**)&phv, g_hv);
    cudaGetSymbolAddress((void**)&po1, g_o1);

    embed_kernel<<<NTOK, 128>>>(tok_emb, pos_emb, ids);

    for (int l = 0; l < NL; l++) {
        ln_kernel<<<NTOK, 256>>>(px, ln1_w + l * E, ln1_b + l * E, ph);
        {
            dim3 g(3 * E / 128, NTOK / 128, 1);
            gemm_tf32<<<g, 256>>>(ph, qkv_w + (long)l * 3 * E * E, nullptr, nullptr,
                                  pqkv, NTOK, 3 * E, E, 0, 0, 0, 0, 0);
        }
        rope_kernel<<<NTOK, 512>>>();
        attn_tile_kernel<<<BB * HN * (T / 128), 256>>>();
        {
            dim3 g(E / 128, NTOK / 128, 1);
            gemm_tf32<<<g, 256>>>(patt, out_w + (long)l * E * E, nullptr, px,
                                  px, NTOK, E, E, 0, 0, 0, 0, 0);
        }
        ln_kernel<<<NTOK, 256>>>(px, ln2_w + l * E, ln2_b + l * E, ph);
        router_kernel<<<NTOK / 8, 256>>>(route_w + (long)l * X * E, route_b + l * X,
                                         noise_w + (long)l * X * E, noise_b + l * X,
                                         rnoise + (long)l * NTOK * X);
        dispatch_kernel<<<X, 256>>>();
        gather_kernel<<<X * CAP, 128>>>();
        {
            dim3 g1(H4 / 128, CAP / 128, X);
            gemm_tf32<<<g1, 256>>>(pein, exp_w1 + (long)l * X * H4 * E,
                                   exp_b1 + (long)l * X * H4, nullptr, pehid,
                                   CAP, H4, E, CAP * E, H4 * E, H4, CAP * H4, 1);
            dim3 g2(E / 128, CAP / 128, X);
            gemm_tf32<<<g2, 256>>>(pehid, exp_w2 + (long)l * X * E * H4,
                                   exp_b2 + (long)l * X * E, nullptr, peout,
                                   CAP, E, H4, CAP * H4, E * H4, E, CAP * E, 0);
        }
        combine_kernel<<<NTOK, 128>>>();
    }

    ln_kernel<<<NTOK, 256>>>(px, lnf_w, lnf_b, ph);
    pool_kernel<<<BB, 256>>>(pool_q);
    gemv_warp<<<(BB * HIGH * 32) / 256, 256>>>(ppool, pool_w, pool_b, phv, BB, HIGH, E);
    gemv_warp<<<(BB * HID * 32) / 256, 256>>>(phv, head_w1, head_b1, po1, BB, HID, HIGH);
    head2_kernel<<<BB, 32>>>(head_w2, head_b2, out);
}

// round 13
// speedup vs baseline: 2.3073x; 1.1625x over previous
#include <cuda_runtime.h>
#include <cuda_bf16.h>
#include <math.h>
#include <stdint.h>

#define E 512
#define T 1024
#define BB 8
#define HN 8
#define DH 64
#define HALF 32
#define NL 4
#define X 8
#define TOPK 2
#define CAP 2048
#define H4 2048
#define NTOK 8192
#define HIGH 32000
#define HID 1024
#define E2 (E / 2)
#define H42 (H4 / 2)

// ---------------- scratch (device globals; no allocation allowed) ----------------
__device__ float g_x[NTOK * E];
__device__ float g_h[NTOK * E];
__device__ float g_qkv[NTOK * 3 * E];
__device__ int   g_topi[NTOK * TOPK];
__device__ float g_gatev[NTOK * TOPK];
__device__ int   g_idx[X * CAP];
__device__ float g_gate[X * CAP];
__device__ int   g_slot[NTOK * TOPK];
__device__ int   g_cnt[X];
__device__ float g_eout[X * CAP * E];
__device__ float g_pool[BB * E];
__device__ float g_hv[BB * HIGH];
__device__ float g_o1[BB * HID];
// packed bf16x2 hi/lo operand buffers
__device__ uint32_t g_pH[NTOK * E2];          // ln1 out / attention out (time-shared)
__device__ uint32_t g_pL[NTOK * E2];
__device__ uint32_t g_einH[X * CAP * E2];
__device__ uint32_t g_einL[X * CAP * E2];
__device__ uint32_t g_ehH[(long)X * CAP * H42];
__device__ uint32_t g_ehL[(long)X * CAP * H42];
__device__ uint32_t g_qwH[3 * E * E2];
__device__ uint32_t g_qwL[3 * E * E2];
__device__ uint32_t g_owH[E * E2];
__device__ uint32_t g_owL[E * E2];
__device__ uint32_t g_w1H[X * H4 * E2];
__device__ uint32_t g_w1L[X * H4 * E2];
__device__ uint32_t g_w2H[X * E * H42];
__device__ uint32_t g_w2L[X * E * H42];

// ---------------- bf16 split helpers ----------------
__device__ __forceinline__ void bsplit2(float x0, float x1, uint32_t& hi, uint32_t& lo) {
    __nv_bfloat16 h0 = __float2bfloat16_rn(x0);
    __nv_bfloat16 h1 = __float2bfloat16_rn(x1);
    float h0f = __bfloat162float(h0), h1f = __bfloat162float(h1);
    __nv_bfloat162 hp; hp.x = h0; hp.y = h1;
    hi = *(uint32_t*)&hp;
    __nv_bfloat16 l0 = __float2bfloat16_rn(x0 - h0f);
    __nv_bfloat16 l1 = __float2bfloat16_rn(x1 - h1f);
    __nv_bfloat162 lp; lp.x = l0; lp.y = l1;
    lo = *(uint32_t*)&lp;
}

__device__ __forceinline__ void mma_bf16(float c[4], uint32_t a0, uint32_t a1,
                                         uint32_t a2, uint32_t a3,
                                         uint32_t b0, uint32_t b1) {
    asm volatile(
        "mma.sync.aligned.m16n8k16.row.col.f32.bf16.bf16.f32 "
        "{%0,%1,%2,%3}, {%4,%5,%6,%7}, {%8,%9}, {%0,%1,%2,%3};"
        : "+f"(c[0]), "+f"(c[1]), "+f"(c[2]), "+f"(c[3])
        : "r"(a0), "r"(a1), "r"(a2), "r"(a3), "r"(b0), "r"(b1));
}

__device__ __forceinline__ void cp16(void* dst, const void* src) {
    uint32_t d = (uint32_t)__cvta_generic_to_shared(dst);
    asm volatile("cp.async.ca.shared.global [%0], [%1], 16;" :: "r"(d), "l"(src));
}

// ---------------- weight/operand split kernel ----------------
__global__ void cvt_split(const float* __restrict__ in, uint32_t* __restrict__ hi,
                          uint32_t* __restrict__ lo, int npairs) {
    int i = blockIdx.x * blockDim.x + threadIdx.x;
    if (i >= npairs) return;
    float2 v = ((const float2*)in)[i];
    uint32_t h, l;
    bsplit2(v.x, v.y, h, l);
    hi[i] = h; lo[i] = l;
}

// ---------------- embed ----------------
__global__ void embed_kernel(const float* __restrict__ tok, const float* __restrict__ pos,
                             const int* __restrict__ ids) {
    int n = blockIdx.x;
    int t = n % T;
    int id = ids[n];
    const float4* te = (const float4*)(tok + (long)id * E);
    const float4* pe = (const float4*)(pos + (long)t * E);
    float4* xr = (float4*)(g_x + (long)n * E);
    int i = threadIdx.x;
    float4 a = te[i], b = pe[i];
    a.x += b.x; a.y += b.y; a.z += b.z; a.w += b.w;
    xr[i] = a;
}

// ---------------- layernorm: optional fp32 and/or packed bf16 hi/lo output ----------------
__global__ void ln_kernel(const float* __restrict__ in, const float* __restrict__ w,
                          const float* __restrict__ b, float* __restrict__ outF,
                          uint32_t* __restrict__ outH, uint32_t* __restrict__ outL) {
    int n = blockIdx.x;
    int tid = threadIdx.x, lane = tid & 31, wid = tid >> 5;
    __shared__ float red[8];
    float2 v = ((const float2*)(in + (long)n * E))[tid];
    float s = v.x + v.y;
    #pragma unroll
    for (int o = 16; o; o >>= 1) s += __shfl_xor_sync(~0u, s, o);
    if (lane == 0) red[wid] = s;
    __syncthreads();
    float tot = 0;
    #pragma unroll
    for (int w8 = 0; w8 < 8; w8++) tot += red[w8];
    float mean = tot * (1.0f / E);
    float d0 = v.x - mean, d1 = v.y - mean;
    float sq = d0 * d0 + d1 * d1;
    __syncthreads();
    #pragma unroll
    for (int o = 16; o; o >>= 1) sq += __shfl_xor_sync(~0u, sq, o);
    if (lane == 0) red[wid] = sq;
    __syncthreads();
    float tv = 0;
    #pragma unroll
    for (int w8 = 0; w8 < 8; w8++) tv += red[w8];
    float inv = rsqrtf(tv * (1.0f / E) + 1e-5f);
    float o0 = d0 * inv * w[2 * tid] + b[2 * tid];
    float o1 = d1 * inv * w[2 * tid + 1] + b[2 * tid + 1];
    if (outF) {
        float2 o; o.x = o0; o.y = o1;
        ((float2*)(outF + (long)n * E))[tid] = o;
    }
    if (outH) {
        uint32_t h, l;
        bsplit2(o0, o1, h, l);
        outH[(long)n * E2 + tid] = h;
        outL[(long)n * E2 + tid] = l;
    }
}

// ---------------- 3xBF16 tensor-core GEMM, cp.async 2-stage pipeline ----------------
// Operands pre-split into packed bf16x2 hi/lo (pair p holds k=2p low half, 2p+1 high).
// C = act(A @ W^T + bias [+resid]); output fp32 (CF) or packed hi/lo (CH/CL).
// 128x128x16 tiles, 256 threads, warp grid 2(M)x4(N), warp tile 64x32 via m16n8k16.
__global__ void __launch_bounds__(256, 2)
gemm_bf3(const uint32_t* __restrict__ AH, const uint32_t* __restrict__ AL,
         const uint32_t* __restrict__ WH, const uint32_t* __restrict__ WL,
         const float* __restrict__ bias, const float* __restrict__ resid,
         float* __restrict__ CF, uint32_t* __restrict__ CH, uint32_t* __restrict__ CL,
         int M, int N, int K2, int aB, int wB, int bB, int cB, int act) {
    int z = blockIdx.z;
    AH += (long)z * aB; AL += (long)z * aB;
    WH += (long)z * wB; WL += (long)z * wB;
    __shared__ uint32_t sAH[2][128][12];
    __shared__ uint32_t sAL[2][128][12];
    __shared__ uint32_t sWH[2][128][12];
    __shared__ uint32_t sWL[2][128][12];
    int tid = threadIdx.x;
    int lane = tid & 31, w = tid >> 5;
    int g = lane >> 2, tig = lane & 3;
    int wm = (w >> 2) * 64, wn = (w & 3) * 32;
    int m0 = blockIdx.y * 128, n0 = blockIdx.x * 128;
    int lrow = tid >> 1, lcol = (tid & 1) * 4;
    float c[4][4][4] = {};

    const uint32_t* Asrc = AH + (long)(m0 + lrow) * K2 + lcol;
    const uint32_t* AsrcL = AL + (long)(m0 + lrow) * K2 + lcol;
    const uint32_t* Wsrc = WH + (long)(n0 + lrow) * K2 + lcol;
    const uint32_t* WsrcL = WL + (long)(n0 + lrow) * K2 + lcol;

    cp16(&sAH[0][lrow][lcol], Asrc);
    cp16(&sAL[0][lrow][lcol], AsrcL);
    cp16(&sWH[0][lrow][lcol], Wsrc);
    cp16(&sWL[0][lrow][lcol], WsrcL);
    asm volatile("cp.async.commit_group;");

    int nk = K2 >> 3;
    for (int kt = 0; kt < nk; kt++) {
        if (kt + 1 < nk) {
            int s = (kt + 1) & 1;
            int ko = (kt + 1) << 3;
            cp16(&sAH[s][lrow][lcol], Asrc + ko);
            cp16(&sAL[s][lrow][lcol], AsrcL + ko);
            cp16(&sWH[s][lrow][lcol], Wsrc + ko);
            cp16(&sWL[s][lrow][lcol], WsrcL + ko);
            asm volatile("cp.async.commit_group;");
            asm volatile("cp.async.wait_group 1;");
        } else {
            asm volatile("cp.async.wait_group 0;");
        }
        __syncthreads();
        int st = kt & 1;
        uint32_t bH[4][2], bL[4][2];
        #pragma unroll
        for (int nf = 0; nf < 4; nf++) {
            int r = wn + nf * 8 + g;
            bH[nf][0] = sWH[st][r][tig];
            bH[nf][1] = sWH[st][r][tig + 4];
            bL[nf][0] = sWL[st][r][tig];
            bL[nf][1] = sWL[st][r][tig + 4];
        }
        #pragma unroll
        for (int mf = 0; mf < 4; mf++) {
            int r = wm + mf * 16 + g;
            uint32_t aH0 = sAH[st][r][tig], aH1 = sAH[st][r + 8][tig];
            uint32_t aH2 = sAH[st][r][tig + 4], aH3 = sAH[st][r + 8][tig + 4];
            uint32_t aL0 = sAL[st][r][tig], aL1 = sAL[st][r + 8][tig];
            uint32_t aL2 = sAL[st][r][tig + 4], aL3 = sAL[st][r + 8][tig + 4];
            #pragma unroll
            for (int nf = 0; nf < 4; nf++) {
                mma_bf16(c[mf][nf], aH0, aH1, aH2, aH3, bL[nf][0], bL[nf][1]);
                mma_bf16(c[mf][nf], aL0, aL1, aL2, aL3, bH[nf][0], bH[nf][1]);
                mma_bf16(c[mf][nf], aH0, aH1, aH2, aH3, bH[nf][0], bH[nf][1]);
            }
        }
        __syncthreads();
    }

    #pragma unroll
    for (int mf = 0; mf < 4; mf++) {
        #pragma unroll
        for (int nf = 0; nf < 4; nf++) {
            int nb = n0 + wn + nf * 8 + tig * 2;
            #pragma unroll
            for (int i = 0; i < 2; i++) {
                int m = m0 + wm + mf * 16 + g + i * 8;
                float v0 = c[mf][nf][i * 2];
                float v1 = c[mf][nf][i * 2 + 1];
                if (bias) {
                    v0 += bias[(long)z * bB + nb];
                    v1 += bias[(long)z * bB + nb + 1];
                }
                if (resid) {
                    v0 += resid[(long)m * N + nb];
                    v1 += resid[(long)m * N + nb + 1];
                }
                if (act) { v0 = fmaxf(v0, 0.0f); v1 = fmaxf(v1, 0.0f); }
                if (CF) {
                    float2 o; o.x = v0; o.y = v1;
                    *(float2*)(CF + (long)z * cB + (long)m * N + nb) = o;
                } else {
                    uint32_t h, l;
                    bsplit2(v0, v1, h, l);
                    long off = (long)z * (cB >> 1) + (long)m * (N >> 1) + (nb >> 1);
                    CH[off] = h;
                    CL[off] = l;
                }
            }
        }
    }
}

// ---------------- RoPE in-place on q,k of g_qkv ----------------
__global__ void rope_kernel() {
    int n = blockIdx.x;
    int tid = threadIdx.x;  // 512
    int which = tid >> 8;
    int rem = tid & 255;
    int h = rem >> 5, j = rem & 31;
    int t = n % T;
    float div = expf(-(float)j * (9.210340371976184f / 32.0f));
    float ang = (float)t * div;
    float c = cosf(ang), s = sinf(ang);
    float* p = g_qkv + (long)n * 3 * E + which * E + h * DH;
    float a1 = p[j], a2 = p[j + HALF];
    p[j] = a1 * c - a2 * s;
    p[j + HALF] = a2 * c + a1 * s;
}

// ---------------- tiled flash attention (packed bf16 hi/lo output) ----------------
// Output in the reference's permuted layout: row t' = h*128 + t/8,
// channel e' = (t%8)*64 + d, split/packed for the out-proj GEMM.
#define KT 64
__global__ void __launch_bounds__(256, 2) attn_tile_kernel() {
    int bidx = blockIdx.x;                  // b*64 + h*8 + qb
    int qb = bidx & 7;
    int h = (bidx >> 3) & 7;
    int b = bidx >> 6;
    int tid = threadIdx.x;
    int warp = tid >> 5, lane = tid & 31;
    int qi = warp * 16 + (lane >> 1);
    int t = qb * 128 + qi;
    int half = lane & 1;
    int n = b * T + t;
    __shared__ float Ks[KT][68];
    __shared__ float Vs[KT][68];
    float q[32];
    const float* qr = g_qkv + (long)n * 3 * E + h * DH + half * 32;
    #pragma unroll
    for (int j = 0; j < 32; j += 4) {
        float4 v = *(const float4*)(qr + j);
        q[j] = v.x * 0.125f; q[j + 1] = v.y * 0.125f;
        q[j + 2] = v.z * 0.125f; q[j + 3] = v.w * 0.125f;
    }
    float m = -INFINITY, lsum = 0.0f, acc[32];
    #pragma unroll
    for (int j = 0; j < 32; j++) acc[j] = 0.0f;
    const float* kvbase = g_qkv + (long)b * T * 3 * E + h * DH;
    for (int s0 = 0; s0 < T; s0 += KT) {
        #pragma unroll
        for (int i = 0; i < 4; i++) {
            int f = tid + 256 * i;
            int r = f >> 4, c4 = (f & 15) * 4;
            const float* krow = kvbase + (long)(s0 + r) * 3 * E + E;
            *(float4*)&Ks[r][c4] = *(const float4*)(krow + c4);
            *(float4*)&Vs[r][c4] = *(const float4*)(krow + E + c4);
        }
        __syncthreads();
        #pragma unroll 2
        for (int s = 0; s < KT; s++) {
            const float* kr = &Ks[s][half * 32];
            float p = 0.0f;
            #pragma unroll
            for (int j = 0; j < 32; j += 4) {
                float4 kv = *(const float4*)(kr + j);
                p += q[j] * kv.x + q[j + 1] * kv.y + q[j + 2] * kv.z + q[j + 3] * kv.w;
            }
            p += __shfl_xor_sync(~0u, p, 1);
            float mn = fmaxf(m, p);
            float corr = __expf(m - mn);
            float w = __expf(p - mn);
            lsum = lsum * corr + w;
            m = mn;
            const float* vr = &Vs[s][half * 32];
            #pragma unroll
            for (int j = 0; j < 32; j += 4) {
                float4 vv = *(const float4*)(vr + j);
                acc[j]     = acc[j]     * corr + w * vv.x;
                acc[j + 1] = acc[j + 1] * corr + w * vv.y;
                acc[j + 2] = acc[j + 2] * corr + w * vv.z;
                acc[j + 3] = acc[j + 3] * corr + w * vv.w;
            }
        }
        __syncthreads();
    }
    float inv = 1.0f / lsum;
    int tp = h * 128 + (t >> 3);
    int ep2 = (t & 7) * 32 + half * 16;          // pair index base
    long base = ((long)b * T + tp) * E2 + ep2;
    #pragma unroll
    for (int j = 0; j < 32; j += 2) {
        uint32_t hh, ll;
        bsplit2(acc[j] * inv, acc[j + 1] * inv, hh, ll);
        g_pH[base + (j >> 1)] = hh;
        g_pL[base + (j >> 1)] = ll;
    }
}

// ---------------- router: warp per token, top-2 + gates ----------------
__global__ void router_kernel(const float* __restrict__ rw, const float* __restrict__ rb,
                              const float* __restrict__ nw, const float* __restrict__ nb,
                              const float* __restrict__ rn) {
    int gw = (blockIdx.x * blockDim.x + threadIdx.x) >> 5;
    int lane = threadIdx.x & 31;
    if (gw >= NTOK) return;
    const float* h = g_h + (long)gw * E;
    float hr[16];
    #pragma unroll
    for (int j = 0; j < 16; j++) hr[j] = h[lane + 32 * j];
    float lg[X], ng[X];
    #pragma unroll
    for (int e = 0; e < X; e++) {
        float a = 0, bn = 0;
        const float* wr = rw + (long)e * E;
        const float* wn = nw + (long)e * E;
        #pragma unroll
        for (int j = 0; j < 16; j++) {
            a += hr[j] * wr[lane + 32 * j];
            bn += hr[j] * wn[lane + 32 * j];
        }
        #pragma unroll
        for (int o = 16; o; o >>= 1) {
            a += __shfl_xor_sync(~0u, a, o);
            bn += __shfl_xor_sync(~0u, bn, o);
        }
        lg[e] = a;
        ng[e] = bn;
    }
    if (lane == 0) {
        float noisy[X];
        #pragma unroll
        for (int e = 0; e < X; e++) {
            float lo = lg[e] + rb[e];
            float nl = ng[e] + nb[e];
            float sp = nl > 0.0f ? nl + log1pf(expf(-nl)) : log1pf(expf(nl));
            noisy[e] = lo + rn[(long)gw * X + e] * sp;
        }
        int b1 = 0; float v1 = noisy[0];
        #pragma unroll
        for (int e = 1; e < X; e++) if (noisy[e] > v1) { v1 = noisy[e]; b1 = e; }
        int b2 = -1; float v2 = -INFINITY;
        #pragma unroll
        for (int e = 0; e < X; e++) if (e != b1 && noisy[e] > v2) { v2 = noisy[e]; b2 = e; }
        float zz = expf(v2 - v1);
        float p1 = 1.0f / (1.0f + zz);
        float p2 = zz / (1.0f + zz);
        g_topi[gw * 2] = b1; g_topi[gw * 2 + 1] = b2;
        g_gatev[gw * 2] = p1; g_gatev[gw * 2 + 1] = p2;
    }
}

// ---------------- dispatch: ordered compaction per expert ----------------
__global__ void dispatch_kernel() {
    int e = blockIdx.x;
    int tid = threadIdx.x, lane = tid & 31, wid = tid >> 5;
    __shared__ int wsum[8];
    __shared__ int sbase;
    if (tid == 0) sbase = 0;
    __syncthreads();
    for (int c = 0; c < NTOK; c += 256) {
        int n = c + tid;
        int k = -1;
        if (g_topi[n * 2] == e) k = 0;
        else if (g_topi[n * 2 + 1] == e) k = 1;
        unsigned bal = __ballot_sync(~0u, k >= 0);
        if (lane == 0) wsum[wid] = __popc(bal);
        __syncthreads();
        int pre = 0, total = 0;
        #pragma unroll
        for (int w8 = 0; w8 < 8; w8++) {
            total += wsum[w8];
            if (w8 < wid) pre += wsum[w8];
        }
        if (k >= 0) {
            int pos = sbase + pre + __popc(bal & ((1u << lane) - 1));
            if (pos < CAP) {
                g_idx[e * CAP + pos] = n;
                g_gate[e * CAP + pos] = g_gatev[n * 2 + k];
                g_slot[n * 2 + k] = e * CAP + pos;
            } else {
                g_slot[n * 2 + k] = -1;
            }
        }
        __syncthreads();
        if (tid == 0) sbase += total;
        __syncthreads();
    }
    if (tid == 0) g_cnt[e] = sbase < CAP ? sbase : CAP;
}

// ---------------- gather expert inputs (packed output) ----------------
__global__ void gather_kernel() {
    int r = blockIdx.x;
    int e = r / CAP, s = r % CAP;
    int i = threadIdx.x;   // 128 threads: each handles one float4 = 2 pairs
    long base = (long)r * E2 + i * 2;
    if (s < g_cnt[e]) {
        float4 f = ((const float4*)(g_h + (long)g_idx[r] * E))[i];
        uint32_t h0, l0, h1, l1;
        bsplit2(f.x, f.y, h0, l0);
        bsplit2(f.z, f.w, h1, l1);
        g_einH[base] = h0; g_einH[base + 1] = h1;
        g_einL[base] = l0; g_einL[base + 1] = l1;
    } else {
        g_einH[base] = 0; g_einH[base + 1] = 0;
        g_einL[base] = 0; g_einL[base + 1] = 0;
    }
}

// ---------------- combine ----------------
__global__ void combine_kernel() {
    int n = blockIdx.x;
    int i = threadIdx.x;
    float4* xr = (float4*)(g_x + (long)n * E);
    float4 v = xr[i];
    #pragma unroll
    for (int k = 0; k < 2; k++) {
        int s = g_slot[n * 2 + k];
        if (s >= 0) {
            float g = g_gate[s];
            float4 eo = ((const float4*)(g_eout + (long)s * E))[i];
            v.x += g * eo.x; v.y += g * eo.y; v.z += g * eo.z; v.w += g * eo.w;
        }
    }
    xr[i] = v;
}

// ---------------- attention pooling ----------------
__global__ void pool_kernel(const float* __restrict__ pq) {
    int b = blockIdx.x;
    int tid = threadIdx.x, lane = tid & 31, wid = tid >> 5;
    __shared__ float s[T];
    __shared__ float red[8];
    const float* hb = g_h + (long)b * T * E;
    for (int t = wid; t < T; t += 8) {
        float acc = 0;
        const float* row = hb + (long)t * E;
        for (int i = lane; i < E; i += 32) acc += pq[i] * row[i];
        #pragma unroll
        for (int o = 16; o; o >>= 1) acc += __shfl_xor_sync(~0u, acc, o);
        if (lane == 0) s[t] = acc * (1.0f / 22.627416997969522f);
    }
    __syncthreads();
    float m = -INFINITY;
    for (int t = tid; t < T; t += 256) m = fmaxf(m, s[t]);
    #pragma unroll
    for (int o = 16; o; o >>= 1) m = fmaxf(m, __shfl_xor_sync(~0u, m, o));
    if (lane == 0) red[wid] = m;
    __syncthreads();
    float mm = red[0];
    #pragma unroll
    for (int w8 = 1; w8 < 8; w8++) mm = fmaxf(mm, red[w8]);
    float sum = 0;
    for (int t = tid; t < T; t += 256) {
        float e2 = expf(s[t] - mm);
        s[t] = e2;
        sum += e2;
    }
    #pragma unroll
    for (int o = 16; o; o >>= 1) sum += __shfl_xor_sync(~0u, sum, o);
    __syncthreads();
    if (lane == 0) red[wid] = sum;
    __syncthreads();
    float tot = 0;
    #pragma unroll
    for (int w8 = 0; w8 < 8; w8++) tot += red[w8];
    float inv = 1.0f / tot;
    for (int e0 = tid; e0 < E; e0 += 256) {
        float acc = 0;
        for (int t = 0; t < T; t++) acc += s[t] * hb[(long)t * E + e0];
        g_pool[(long)b * E + e0] = acc * inv;
    }
}

// ---------------- warp-per-output GEMV ----------------
__global__ void gemv_warp(const float* __restrict__ A, const float* __restrict__ W,
                          const float* __restrict__ bias, float* __restrict__ C,
                          int M, int N, int Kd) {
    int gw = (blockIdx.x * blockDim.x + threadIdx.x) >> 5;
    int lane = threadIdx.x & 31;
    if (gw >= M * N) return;
    int m = gw / N, n = gw % N;
    const float* a = A + (long)m * Kd;
    const float* w = W + (long)n * Kd;
    float acc = 0;
    for (int i = lane; i < Kd; i += 32) acc += a[i] * w[i];
    #pragma unroll
    for (int o = 16; o; o >>= 1) acc += __shfl_xor_sync(~0u, acc, o);
    if (lane == 0) C[(long)m * N + n] = acc + (bias ? bias[n] : 0.0f);
}

// ---------------- final head ----------------
__global__ void head2_kernel(const float* __restrict__ w2, const float* __restrict__ b2,
                             float* __restrict__ out) {
    int b = blockIdx.x;
    int lane = threadIdx.x;
    float acc = 0;
    for (int i = lane; i < HID; i += 32) acc += fmaxf(g_o1[(long)b * HID + i], 0.0f) * w2[i];
    #pragma unroll
    for (int o = 16; o; o >>= 1) acc += __shfl_xor_sync(~0u, acc, o);
    if (lane == 0) out[b] = acc + b2[0];
}

// ---------------- host ----------------
extern "C" void kernel_launch(void* const* d_in, const int* in_sizes, int n_in,
                              void* d_out, int out_size) {
    const float* tok_emb = (const float*)d_in[0];
    const float* pos_emb = (const float*)d_in[1];
    const float* ln1_w = (const float*)d_in[2];
    const float* ln1_b = (const float*)d_in[3];
    const float* ln2_w = (const float*)d_in[4];
    const float* ln2_b = (const float*)d_in[5];
    const float* qkv_w = (const float*)d_in[6];
    const float* out_w = (const float*)d_in[7];
    const float* route_w = (const float*)d_in[8];
    const float* route_b = (const float*)d_in[9];
    const float* noise_w = (const float*)d_in[10];
    const float* noise_b = (const float*)d_in[11];
    const float* exp_w1 = (const float*)d_in[12];
    const float* exp_b1 = (const float*)d_in[13];
    const float* exp_w2 = (const float*)d_in[14];
    const float* exp_b2 = (const float*)d_in[15];
    const float* lnf_w = (const float*)d_in[16];
    const float* lnf_b = (const float*)d_in[17];
    const float* pool_q = (const float*)d_in[18];
    const float* pool_w = (const float*)d_in[19];
    const float* pool_b = (const float*)d_in[20];
    const float* head_w1 = (const float*)d_in[21];
    const float* head_b1 = (const float*)d_in[22];
    const float* head_w2 = (const float*)d_in[23];
    const float* head_b2 = (const float*)d_in[24];
    const int* ids = (const int*)d_in[25];
    const float* rnoise = (const float*)d_in[26];
    float* out = (float*)d_out;

    float *px, *ph, *pqkv, *peout, *ppool, *phv, *po1;
    uint32_t *ppH, *ppL, *peinH, *peinL, *pehH, *pehL;
    uint32_t *pqwH, *pqwL, *powH, *powL, *pw1H, *pw1L, *pw2H, *pw2L;
    cudaGetSymbolAddress((void**)&px, g_x);
    cudaGetSymbolAddress((void**)&ph, g_h);
    cudaGetSymbolAddress((void**)&pqkv, g_qkv);
    cudaGetSymbolAddress((void**)&peout, g_eout);
    cudaGetSymbolAddress((void**)&ppool, g_pool);
    cudaGetSymbolAddress((void**)&phv, g_hv);
    cudaGetSymbolAddress((void**)&po1, g_o1);
    cudaGetSymbolAddress((void**)&ppH, g_pH);
    cudaGetSymbolAddress((void**)&ppL, g_pL);
    cudaGetSymbolAddress((void**)&peinH, g_einH);
    cudaGetSymbolAddress((void**)&peinL, g_einL);
    cudaGetSymbolAddress((void**)&pehH, g_ehH);
    cudaGetSymbolAddress((void**)&pehL, g_ehL);
    cudaGetSymbolAddress((void**)&pqwH, g_qwH);
    cudaGetSymbolAddress((void**)&pqwL, g_qwL);
    cudaGetSymbolAddress((void**)&powH, g_owH);
    cudaGetSymbolAddress((void**)&powL, g_owL);
    cudaGetSymbolAddress((void**)&pw1H, g_w1H);
    cudaGetSymbolAddress((void**)&pw1L, g_w1L);
    cudaGetSymbolAddress((void**)&pw2H, g_w2H);
    cudaGetSymbolAddress((void**)&pw2L, g_w2L);

    embed_kernel<<<NTOK, 128>>>(tok_emb, pos_emb, ids);

    for (int l = 0; l < NL; l++) {
        // weight splits for this layer
        cvt_split<<<(3 * E * E2 + 255) / 256, 256>>>(qkv_w + (long)l * 3 * E * E, pqwH, pqwL, 3 * E * E2);
        cvt_split<<<(E * E2 + 255) / 256, 256>>>(out_w + (long)l * E * E, powH, powL, E * E2);
        cvt_split<<<(X * H4 * E2 + 255) / 256, 256>>>(exp_w1 + (long)l * X * H4 * E, pw1H, pw1L, X * H4 * E2);
        cvt_split<<<(X * E * H42 + 255) / 256, 256>>>(exp_w2 + (long)l * X * E * H4, pw2H, pw2L, X * E * H42);

        // LN1 -> packed
        ln_kernel<<<NTOK, 256>>>(px, ln1_w + l * E, ln1_b + l * E, nullptr, ppH, ppL);
        // QKV GEMM
        {
            dim3 g(3 * E / 128, NTOK / 128, 1);
            gemm_bf3<<<g, 256>>>(ppH, ppL, pqwH, pqwL, nullptr, nullptr,
                                 pqkv, nullptr, nullptr, NTOK, 3 * E, E2, 0, 0, 0, 0, 0);
        }
        rope_kernel<<<NTOK, 512>>>();
        attn_tile_kernel<<<BB * HN * (T / 128), 256>>>();   // writes ppH/ppL
        // out-proj + residual
        {
            dim3 g(E / 128, NTOK / 128, 1);
            gemm_bf3<<<g, 256>>>(ppH, ppL, powH, powL, nullptr, px,
                                 px, nullptr, nullptr, NTOK, E, E2, 0, 0, 0, 0, 0);
        }
        // LN2 -> fp32 (router, gather)
        ln_kernel<<<NTOK, 256>>>(px, ln2_w + l * E, ln2_b + l * E, ph, nullptr, nullptr);
        router_kernel<<<NTOK / 8, 256>>>(route_w + (long)l * X * E, route_b + l * X,
                                         noise_w + (long)l * X * E, noise_b + l * X,
                                         rnoise + (long)l * NTOK * X);
        dispatch_kernel<<<X, 256>>>();
        gather_kernel<<<X * CAP, 128>>>();                   // writes packed ein
        // expert FFN
        {
            dim3 g1(H4 / 128, CAP / 128, X);
            gemm_bf3<<<g1, 256>>>(peinH, peinL, pw1H, pw1L,
                                  exp_b1 + (long)l * X * H4, nullptr,
                                  nullptr, pehH, pehL,
                                  CAP, H4, E2, CAP * E2, H4 * E2, H4, CAP * H4, 1);
            dim3 g2(E / 128, CAP / 128, X);
            gemm_bf3<<<g2, 256>>>(pehH, pehL, pw2H, pw2L,
                                  exp_b2 + (long)l * X * E, nullptr,
                                  peout, nullptr, nullptr,
                                  CAP, E, H42, CAP * H42, E * H42, E, CAP * E, 0);
        }
        combine_kernel<<<NTOK, 128>>>();
    }

    ln_kernel<<<NTOK, 256>>>(px, lnf_w, lnf_b, ph, nullptr, nullptr);
    pool_kernel<<<BB, 256>>>(pool_q);
    gemv_warp<<<(BB * HIGH * 32) / 256, 256>>>(ppool, pool_w, pool_b, phv, BB, HIGH, E);
    gemv_warp<<<(BB * HID * 32) / 256, 256>>>(phv, head_w1, head_b1, po1, BB, HID, HIGH);
    head2_kernel<<<BB, 32>>>(head_w2, head_b2, out);
}

// round 15
// speedup vs baseline: 2.3848x; 1.0336x over previous
#include <cuda_runtime.h>
#include <cuda_bf16.h>
#include <math.h>
#include <stdint.h>

#define E 512
#define T 1024
#define BB 8
#define HN 8
#define DH 64
#define HALF 32
#define NL 4
#define X 8
#define TOPK 2
#define CAP 2048
#define H4 2048
#define NTOK 8192
#define HIGH 32000
#define HID 1024
#define E2 (E / 2)
#define H42 (H4 / 2)

// ---------------- scratch (device globals; no allocation allowed) ----------------
__device__ float g_x[NTOK * E];
__device__ float g_h[NTOK * E];
__device__ float g_qkv[NTOK * 3 * E];
__device__ int   g_topi[NTOK * TOPK];
__device__ float g_gatev[NTOK * TOPK];
__device__ int   g_idx[X * CAP];
__device__ float g_gate[X * CAP];
__device__ int   g_slot[NTOK * TOPK];
__device__ int   g_cnt[X];
__device__ float g_eout[X * CAP * E];
__device__ float g_pool[BB * E];
__device__ float g_hv[BB * HIGH];
__device__ float g_o1[BB * HID];
// packed bf16x2 hi/lo operand buffers
__device__ uint32_t g_pH[NTOK * E2];
__device__ uint32_t g_pL[NTOK * E2];
__device__ uint32_t g_einH[X * CAP * E2];
__device__ uint32_t g_einL[X * CAP * E2];
__device__ uint32_t g_ehH[(long)X * CAP * H42];
__device__ uint32_t g_ehL[(long)X * CAP * H42];
__device__ uint32_t g_qwH[3 * E * E2];
__device__ uint32_t g_qwL[3 * E * E2];
__device__ uint32_t g_owH[E * E2];
__device__ uint32_t g_owL[E * E2];
__device__ uint32_t g_w1H[X * H4 * E2];
__device__ uint32_t g_w1L[X * H4 * E2];
__device__ uint32_t g_w2H[X * E * H42];
__device__ uint32_t g_w2L[X * E * H42];

// ---------------- bf16 split helpers ----------------
__device__ __forceinline__ void bsplit2(float x0, float x1, uint32_t& hi, uint32_t& lo) {
    __nv_bfloat16 h0 = __float2bfloat16_rn(x0);
    __nv_bfloat16 h1 = __float2bfloat16_rn(x1);
    float h0f = __bfloat162float(h0), h1f = __bfloat162float(h1);
    __nv_bfloat162 hp; hp.x = h0; hp.y = h1;
    hi = *(uint32_t*)&hp;
    __nv_bfloat16 l0 = __float2bfloat16_rn(x0 - h0f);
    __nv_bfloat16 l1 = __float2bfloat16_rn(x1 - h1f);
    __nv_bfloat162 lp; lp.x = l0; lp.y = l1;
    lo = *(uint32_t*)&lp;
}

__device__ __forceinline__ void mma_bf16(float c[4], uint32_t a0, uint32_t a1,
                                         uint32_t a2, uint32_t a3,
                                         uint32_t b0, uint32_t b1) {
    asm volatile(
        "mma.sync.aligned.m16n8k16.row.col.f32.bf16.bf16.f32 "
        "{%0,%1,%2,%3}, {%4,%5,%6,%7}, {%8,%9}, {%0,%1,%2,%3};"
        : "+f"(c[0]), "+f"(c[1]), "+f"(c[2]), "+f"(c[3])
        : "r"(a0), "r"(a1), "r"(a2), "r"(a3), "r"(b0), "r"(b1));
}

__device__ __forceinline__ void cp16(void* dst, const void* src) {
    uint32_t d = (uint32_t)__cvta_generic_to_shared(dst);
    asm volatile("cp.async.ca.shared.global [%0], [%1], 16;" :: "r"(d), "l"(src));
}

__device__ __forceinline__ void ldsm4(uint32_t& r0, uint32_t& r1, uint32_t& r2,
                                      uint32_t& r3, uint32_t saddr) {
    asm volatile("ldmatrix.sync.aligned.m8n8.x4.shared.b16 {%0,%1,%2,%3}, [%4];"
                 : "=r"(r0), "=r"(r1), "=r"(r2), "=r"(r3) : "r"(saddr));
}

// ---------------- weight/operand split kernel ----------------
__global__ void cvt_split(const float* __restrict__ in, uint32_t* __restrict__ hi,
                          uint32_t* __restrict__ lo, int npairs) {
    int i = blockIdx.x * blockDim.x + threadIdx.x;
    if (i >= npairs) return;
    float2 v = ((const float2*)in)[i];
    uint32_t h, l;
    bsplit2(v.x, v.y, h, l);
    hi[i] = h; lo[i] = l;
}

// ---------------- embed ----------------
__global__ void embed_kernel(const float* __restrict__ tok, const float* __restrict__ pos,
                             const int* __restrict__ ids) {
    int n = blockIdx.x;
    int t = n % T;
    int id = ids[n];
    const float4* te = (const float4*)(tok + (long)id * E);
    const float4* pe = (const float4*)(pos + (long)t * E);
    float4* xr = (float4*)(g_x + (long)n * E);
    int i = threadIdx.x;
    float4 a = te[i], b = pe[i];
    a.x += b.x; a.y += b.y; a.z += b.z; a.w += b.w;
    xr[i] = a;
}

// ---------------- layernorm: optional fp32 and/or packed bf16 hi/lo output ----------------
__global__ void ln_kernel(const float* __restrict__ in, const float* __restrict__ w,
                          const float* __restrict__ b, float* __restrict__ outF,
                          uint32_t* __restrict__ outH, uint32_t* __restrict__ outL) {
    int n = blockIdx.x;
    int tid = threadIdx.x, lane = tid & 31, wid = tid >> 5;
    __shared__ float red[8];
    float2 v = ((const float2*)(in + (long)n * E))[tid];
    float s = v.x + v.y;
    #pragma unroll
    for (int o = 16; o; o >>= 1) s += __shfl_xor_sync(~0u, s, o);
    if (lane == 0) red[wid] = s;
    __syncthreads();
    float tot = 0;
    #pragma unroll
    for (int w8 = 0; w8 < 8; w8++) tot += red[w8];
    float mean = tot * (1.0f / E);
    float d0 = v.x - mean, d1 = v.y - mean;
    float sq = d0 * d0 + d1 * d1;
    __syncthreads();
    #pragma unroll
    for (int o = 16; o; o >>= 1) sq += __shfl_xor_sync(~0u, sq, o);
    if (lane == 0) red[wid] = sq;
    __syncthreads();
    float tv = 0;
    #pragma unroll
    for (int w8 = 0; w8 < 8; w8++) tv += red[w8];
    float inv = rsqrtf(tv * (1.0f / E) + 1e-5f);
    float o0 = d0 * inv * w[2 * tid] + b[2 * tid];
    float o1 = d1 * inv * w[2 * tid + 1] + b[2 * tid + 1];
    if (outF) {
        float2 o; o.x = o0; o.y = o1;
        ((float2*)(outF + (long)n * E))[tid] = o;
    }
    if (outH) {
        uint32_t h, l;
        bsplit2(o0, o1, h, l);
        outH[(long)n * E2 + tid] = h;
        outL[(long)n * E2 + tid] = l;
    }
}

// ---------------- 3xBF16 tensor-core GEMM: cp.async pipeline + ldmatrix ----------------
// Operands pre-split into packed bf16x2 hi/lo. C = act(A @ W^T + bias [+resid]);
// output fp32 (CF) or packed hi/lo (CH/CL). 128x128x16 tiles, 256 threads,
// warp grid 2(M)x4(N), warp tile 64x32 via m16n8k16.
__global__ void __launch_bounds__(256, 2)
gemm_bf3(const uint32_t* __restrict__ AH, const uint32_t* __restrict__ AL,
         const uint32_t* __restrict__ WH, const uint32_t* __restrict__ WL,
         const float* __restrict__ bias, const float* __restrict__ resid,
         float* __restrict__ CF, uint32_t* __restrict__ CH, uint32_t* __restrict__ CL,
         int M, int N, int K2, int aB, int wB, int bB, int cB, int act) {
    int z = blockIdx.z;
    AH += (long)z * aB; AL += (long)z * aB;
    WH += (long)z * wB; WL += (long)z * wB;
    __shared__ uint32_t sAH[2][128][12];
    __shared__ uint32_t sAL[2][128][12];
    __shared__ uint32_t sWH[2][128][12];
    __shared__ uint32_t sWL[2][128][12];
    int tid = threadIdx.x;
    int lane = tid & 31, w = tid >> 5;
    int g = lane >> 2, tig = lane & 3;
    int wm = (w >> 2) * 64, wn = (w & 3) * 32;
    int m0 = blockIdx.y * 128, n0 = blockIdx.x * 128;
    int lrow = tid >> 1, lcol = (tid & 1) * 4;
    float c[4][4][4] = {};

    const uint32_t* Asrc = AH + (long)(m0 + lrow) * K2 + lcol;
    const uint32_t* AsrcL = AL + (long)(m0 + lrow) * K2 + lcol;
    const uint32_t* Wsrc = WH + (long)(n0 + lrow) * K2 + lcol;
    const uint32_t* WsrcL = WL + (long)(n0 + lrow) * K2 + lcol;

    // ldmatrix per-lane addresses (stage 0); stage stride = 128*12*4 bytes
    int l7 = lane & 7, sub = lane >> 3;
    int nfo = sub >> 1, colB = (sub & 1) * 4;
    int rA = wm + l7 + (sub & 1) * 8;
    int colA = (sub >> 1) * 4;
    uint32_t adrB_H0 = (uint32_t)__cvta_generic_to_shared(&sWH[0][wn + nfo * 8 + l7][colB]);
    uint32_t adrB_H1 = (uint32_t)__cvta_generic_to_shared(&sWH[0][wn + 16 + nfo * 8 + l7][colB]);
    uint32_t adrB_L0 = (uint32_t)__cvta_generic_to_shared(&sWL[0][wn + nfo * 8 + l7][colB]);
    uint32_t adrB_L1 = (uint32_t)__cvta_generic_to_shared(&sWL[0][wn + 16 + nfo * 8 + l7][colB]);
    uint32_t adrA_H = (uint32_t)__cvta_generic_to_shared(&sAH[0][rA][colA]);
    uint32_t adrA_L = (uint32_t)__cvta_generic_to_shared(&sAL[0][rA][colA]);
    const uint32_t SSTR = 128 * 12 * 4;

    cp16(&sAH[0][lrow][lcol], Asrc);
    cp16(&sAL[0][lrow][lcol], AsrcL);
    cp16(&sWH[0][lrow][lcol], Wsrc);
    cp16(&sWL[0][lrow][lcol], WsrcL);
    asm volatile("cp.async.commit_group;");

    int nk = K2 >> 3;
    for (int kt = 0; kt < nk; kt++) {
        if (kt + 1 < nk) {
            int s = (kt + 1) & 1;
            int ko = (kt + 1) << 3;
            cp16(&sAH[s][lrow][lcol], Asrc + ko);
            cp16(&sAL[s][lrow][lcol], AsrcL + ko);
            cp16(&sWH[s][lrow][lcol], Wsrc + ko);
            cp16(&sWL[s][lrow][lcol], WsrcL + ko);
            asm volatile("cp.async.commit_group;");
            asm volatile("cp.async.wait_group 1;");
        } else {
            asm volatile("cp.async.wait_group 0;");
        }
        __syncthreads();
        uint32_t so = (kt & 1) * SSTR;
        uint32_t bH[4][2], bL[4][2];
        ldsm4(bH[0][0], bH[0][1], bH[1][0], bH[1][1], adrB_H0 + so);
        ldsm4(bH[2][0], bH[2][1], bH[3][0], bH[3][1], adrB_H1 + so);
        ldsm4(bL[0][0], bL[0][1], bL[1][0], bL[1][1], adrB_L0 + so);
        ldsm4(bL[2][0], bL[2][1], bL[3][0], bL[3][1], adrB_L1 + so);
        #pragma unroll
        for (int mf = 0; mf < 4; mf++) {
            uint32_t aH0, aH1, aH2, aH3, aL0, aL1, aL2, aL3;
            ldsm4(aH0, aH1, aH2, aH3, adrA_H + so + mf * (16 * 12 * 4));
            ldsm4(aL0, aL1, aL2, aL3, adrA_L + so + mf * (16 * 12 * 4));
            #pragma unroll
            for (int nf = 0; nf < 4; nf++) {
                mma_bf16(c[mf][nf], aH0, aH1, aH2, aH3, bL[nf][0], bL[nf][1]);
                mma_bf16(c[mf][nf], aL0, aL1, aL2, aL3, bH[nf][0], bH[nf][1]);
                mma_bf16(c[mf][nf], aH0, aH1, aH2, aH3, bH[nf][0], bH[nf][1]);
            }
        }
        __syncthreads();
    }

    #pragma unroll
    for (int mf = 0; mf < 4; mf++) {
        #pragma unroll
        for (int nf = 0; nf < 4; nf++) {
            int nb = n0 + wn + nf * 8 + tig * 2;
            #pragma unroll
            for (int i = 0; i < 2; i++) {
                int m = m0 + wm + mf * 16 + g + i * 8;
                float v0 = c[mf][nf][i * 2];
                float v1 = c[mf][nf][i * 2 + 1];
                if (bias) {
                    v0 += bias[(long)z * bB + nb];
                    v1 += bias[(long)z * bB + nb + 1];
                }
                if (resid) {
                    v0 += resid[(long)m * N + nb];
                    v1 += resid[(long)m * N + nb + 1];
                }
                if (act) { v0 = fmaxf(v0, 0.0f); v1 = fmaxf(v1, 0.0f); }
                if (CF) {
                    float2 o; o.x = v0; o.y = v1;
                    *(float2*)(CF + (long)z * cB + (long)m * N + nb) = o;
                } else {
                    uint32_t h, l;
                    bsplit2(v0, v1, h, l);
                    long off = (long)z * (cB >> 1) + (long)m * (N >> 1) + (nb >> 1);
                    CH[off] = h;
                    CL[off] = l;
                }
            }
        }
    }
}

// ---------------- RoPE in-place on q,k of g_qkv ----------------
__global__ void rope_kernel() {
    int n = blockIdx.x;
    int tid = threadIdx.x;  // 512
    int which = tid >> 8;
    int rem = tid & 255;
    int h = rem >> 5, j = rem & 31;
    int t = n % T;
    float div = expf(-(float)j * (9.210340371976184f / 32.0f));
    float ang = (float)t * div;
    float c = cosf(ang), s = sinf(ang);
    float* p = g_qkv + (long)n * 3 * E + which * E + h * DH;
    float a1 = p[j], a2 = p[j + HALF];
    p[j] = a1 * c - a2 * s;
    p[j + HALF] = a2 * c + a1 * s;
}

// ---------------- tiled flash attention (packed bf16 hi/lo output) ----------------
#define KT 64
__global__ void __launch_bounds__(256, 2) attn_tile_kernel() {
    int bidx = blockIdx.x;                  // b*64 + h*8 + qb
    int qb = bidx & 7;
    int h = (bidx >> 3) & 7;
    int b = bidx >> 6;
    int tid = threadIdx.x;
    int warp = tid >> 5, lane = tid & 31;
    int qi = warp * 16 + (lane >> 1);
    int t = qb * 128 + qi;
    int half = lane & 1;
    int n = b * T + t;
    __shared__ float Ks[KT][68];
    __shared__ float Vs[KT][68];
    float q[32];
    const float* qr = g_qkv + (long)n * 3 * E + h * DH + half * 32;
    #pragma unroll
    for (int j = 0; j < 32; j += 4) {
        float4 v = *(const float4*)(qr + j);
        q[j] = v.x * 0.125f; q[j + 1] = v.y * 0.125f;
        q[j + 2] = v.z * 0.125f; q[j + 3] = v.w * 0.125f;
    }
    float m = -INFINITY, lsum = 0.0f, acc[32];
    #pragma unroll
    for (int j = 0; j < 32; j++) acc[j] = 0.0f;
    const float* kvbase = g_qkv + (long)b * T * 3 * E + h * DH;
    for (int s0 = 0; s0 < T; s0 += KT) {
        #pragma unroll
        for (int i = 0; i < 4; i++) {
            int f = tid + 256 * i;
            int r = f >> 4, c4 = (f & 15) * 4;
            const float* krow = kvbase + (long)(s0 + r) * 3 * E + E;
            *(float4*)&Ks[r][c4] = *(const float4*)(krow + c4);
            *(float4*)&Vs[r][c4] = *(const float4*)(krow + E + c4);
        }
        __syncthreads();
        #pragma unroll 2
        for (int s = 0; s < KT; s++) {
            const float* kr = &Ks[s][half * 32];
            float p = 0.0f;
            #pragma unroll
            for (int j = 0; j < 32; j += 4) {
                float4 kv = *(const float4*)(kr + j);
                p += q[j] * kv.x + q[j + 1] * kv.y + q[j + 2] * kv.z + q[j + 3] * kv.w;
            }
            p += __shfl_xor_sync(~0u, p, 1);
            float mn = fmaxf(m, p);
            float corr = __expf(m - mn);
            float w = __expf(p - mn);
            lsum = lsum * corr + w;
            m = mn;
            const float* vr = &Vs[s][half * 32];
            #pragma unroll
            for (int j = 0; j < 32; j += 4) {
                float4 vv = *(const float4*)(vr + j);
                acc[j]     = acc[j]     * corr + w * vv.x;
                acc[j + 1] = acc[j + 1] * corr + w * vv.y;
                acc[j + 2] = acc[j + 2] * corr + w * vv.z;
                acc[j + 3] = acc[j + 3] * corr + w * vv.w;
            }
        }
        __syncthreads();
    }
    float inv = 1.0f / lsum;
    int tp = h * 128 + (t >> 3);
    int ep2 = (t & 7) * 32 + half * 16;
    long base = ((long)b * T + tp) * E2 + ep2;
    #pragma unroll
    for (int j = 0; j < 32; j += 2) {
        uint32_t hh, ll;
        bsplit2(acc[j] * inv, acc[j + 1] * inv, hh, ll);
        g_pH[base + (j >> 1)] = hh;
        g_pL[base + (j >> 1)] = ll;
    }
}

// ---------------- router: warp per token, top-2 + gates ----------------
__global__ void router_kernel(const float* __restrict__ rw, const float* __restrict__ rb,
                              const float* __restrict__ nw, const float* __restrict__ nb,
                              const float* __restrict__ rn) {
    int gw = (blockIdx.x * blockDim.x + threadIdx.x) >> 5;
    int lane = threadIdx.x & 31;
    if (gw >= NTOK) return;
    const float* h = g_h + (long)gw * E;
    float hr[16];
    #pragma unroll
    for (int j = 0; j < 16; j++) hr[j] = h[lane + 32 * j];
    float lg[X], ng[X];
    #pragma unroll
    for (int e = 0; e < X; e++) {
        float a = 0, bn = 0;
        const float* wr = rw + (long)e * E;
        const float* wn = nw + (long)e * E;
        #pragma unroll
        for (int j = 0; j < 16; j++) {
            a += hr[j] * wr[lane + 32 * j];
            bn += hr[j] * wn[lane + 32 * j];
        }
        #pragma unroll
        for (int o = 16; o; o >>= 1) {
            a += __shfl_xor_sync(~0u, a, o);
            bn += __shfl_xor_sync(~0u, bn, o);
        }
        lg[e] = a;
        ng[e] = bn;
    }
    if (lane == 0) {
        float noisy[X];
        #pragma unroll
        for (int e = 0; e < X; e++) {
            float lo = lg[e] + rb[e];
            float nl = ng[e] + nb[e];
            float sp = nl > 0.0f ? nl + log1pf(expf(-nl)) : log1pf(expf(nl));
            noisy[e] = lo + rn[(long)gw * X + e] * sp;
        }
        int b1 = 0; float v1 = noisy[0];
        #pragma unroll
        for (int e = 1; e < X; e++) if (noisy[e] > v1) { v1 = noisy[e]; b1 = e; }
        int b2 = -1; float v2 = -INFINITY;
        #pragma unroll
        for (int e = 0; e < X; e++) if (e != b1 && noisy[e] > v2) { v2 = noisy[e]; b2 = e; }
        float zz = expf(v2 - v1);
        float p1 = 1.0f / (1.0f + zz);
        float p2 = zz / (1.0f + zz);
        g_topi[gw * 2] = b1; g_topi[gw * 2 + 1] = b2;
        g_gatev[gw * 2] = p1; g_gatev[gw * 2 + 1] = p2;
    }
}

// ---------------- dispatch: ordered compaction per expert ----------------
__global__ void dispatch_kernel() {
    int e = blockIdx.x;
    int tid = threadIdx.x, lane = tid & 31, wid = tid >> 5;
    __shared__ int wsum[8];
    __shared__ int sbase;
    if (tid == 0) sbase = 0;
    __syncthreads();
    for (int c = 0; c < NTOK; c += 256) {
        int n = c + tid;
        int k = -1;
        if (g_topi[n * 2] == e) k = 0;
        else if (g_topi[n * 2 + 1] == e) k = 1;
        unsigned bal = __ballot_sync(~0u, k >= 0);
        if (lane == 0) wsum[wid] = __popc(bal);
        __syncthreads();
        int pre = 0, total = 0;
        #pragma unroll
        for (int w8 = 0; w8 < 8; w8++) {
            total += wsum[w8];
            if (w8 < wid) pre += wsum[w8];
        }
        if (k >= 0) {
            int pos = sbase + pre + __popc(bal & ((1u << lane) - 1));
            if (pos < CAP) {
                g_idx[e * CAP + pos] = n;
                g_gate[e * CAP + pos] = g_gatev[n * 2 + k];
                g_slot[n * 2 + k] = e * CAP + pos;
            } else {
                g_slot[n * 2 + k] = -1;
            }
        }
        __syncthreads();
        if (tid == 0) sbase += total;
        __syncthreads();
    }
    if (tid == 0) g_cnt[e] = sbase < CAP ? sbase : CAP;
}

// ---------------- gather expert inputs (packed output) ----------------
__global__ void gather_kernel() {
    int r = blockIdx.x;
    int e = r / CAP, s = r % CAP;
    int i = threadIdx.x;
    long base = (long)r * E2 + i * 2;
    if (s < g_cnt[e]) {
        float4 f = ((const float4*)(g_h + (long)g_idx[r] * E))[i];
        uint32_t h0, l0, h1, l1;
        bsplit2(f.x, f.y, h0, l0);
        bsplit2(f.z, f.w, h1, l1);
        g_einH[base] = h0; g_einH[base + 1] = h1;
        g_einL[base] = l0; g_einL[base + 1] = l1;
    } else {
        g_einH[base] = 0; g_einH[base + 1] = 0;
        g_einL[base] = 0; g_einL[base + 1] = 0;
    }
}

// ---------------- combine ----------------
__global__ void combine_kernel() {
    int n = blockIdx.x;
    int i = threadIdx.x;
    float4* xr = (float4*)(g_x + (long)n * E);
    float4 v = xr[i];
    #pragma unroll
    for (int k = 0; k < 2; k++) {
        int s = g_slot[n * 2 + k];
        if (s >= 0) {
            float g = g_gate[s];
            float4 eo = ((const float4*)(g_eout + (long)s * E))[i];
            v.x += g * eo.x; v.y += g * eo.y; v.z += g * eo.z; v.w += g * eo.w;
        }
    }
    xr[i] = v;
}

// ---------------- attention pooling ----------------
__global__ void pool_kernel(const float* __restrict__ pq) {
    int b = blockIdx.x;
    int tid = threadIdx.x, lane = tid & 31, wid = tid >> 5;
    __shared__ float s[T];
    __shared__ float red[8];
    const float* hb = g_h + (long)b * T * E;
    for (int t = wid; t < T; t += 8) {
        float acc = 0;
        const float* row = hb + (long)t * E;
        for (int i = lane; i < E; i += 32) acc += pq[i] * row[i];
        #pragma unroll
        for (int o = 16; o; o >>= 1) acc += __shfl_xor_sync(~0u, acc, o);
        if (lane == 0) s[t] = acc * (1.0f / 22.627416997969522f);
    }
    __syncthreads();
    float m = -INFINITY;
    for (int t = tid; t < T; t += 256) m = fmaxf(m, s[t]);
    #pragma unroll
    for (int o = 16; o; o >>= 1) m = fmaxf(m, __shfl_xor_sync(~0u, m, o));
    if (lane == 0) red[wid] = m;
    __syncthreads();
    float mm = red[0];
    #pragma unroll
    for (int w8 = 1; w8 < 8; w8++) mm = fmaxf(mm, red[w8]);
    float sum = 0;
    for (int t = tid; t < T; t += 256) {
        float e2 = expf(s[t] - mm);
        s[t] = e2;
        sum += e2;
    }
    #pragma unroll
    for (int o = 16; o; o >>= 1) sum += __shfl_xor_sync(~0u, sum, o);
    __syncthreads();
    if (lane == 0) red[wid] = sum;
    __syncthreads();
    float tot = 0;
    #pragma unroll
    for (int w8 = 0; w8 < 8; w8++) tot += red[w8];
    float inv = 1.0f / tot;
    for (int e0 = tid; e0 < E; e0 += 256) {
        float acc = 0;
        for (int t = 0; t < T; t++) acc += s[t] * hb[(long)t * E + e0];
        g_pool[(long)b * E + e0] = acc * inv;
    }
}

// ---------------- warp-per-column GEMV with m-loop (reads W once) ----------------
// C[m][n] = A[m][:] . W[n][:] + bias[n], m < 8. K % 128 == 0.
__global__ void gemv_mrow(const float* __restrict__ A, const float* __restrict__ W,
                          const float* __restrict__ bias, float* __restrict__ C,
                          int N, int Kd) {
    int gw = (blockIdx.x * blockDim.x + threadIdx.x) >> 5;
    int lane = threadIdx.x & 31;
    if (gw >= N) return;
    const float4* wr = (const float4*)(W + (long)gw * Kd);
    float acc[8] = {};
    int steps = Kd >> 7;             // K/128
    for (int j = 0; j < steps; j++) {
        int idx = lane + 32 * j;
        float4 wv = wr[idx];
        #pragma unroll
        for (int m = 0; m < 8; m++) {
            float4 av = ((const float4*)(A + (long)m * Kd))[idx];
            acc[m] += av.x * wv.x + av.y * wv.y + av.z * wv.z + av.w * wv.w;
        }
    }
    #pragma unroll
    for (int m = 0; m < 8; m++) {
        #pragma unroll
        for (int o = 16; o; o >>= 1) acc[m] += __shfl_xor_sync(~0u, acc[m], o);
    }
    if (lane == 0) {
        float bv = bias ? bias[gw] : 0.0f;
        #pragma unroll
        for (int m = 0; m < 8; m++) C[(long)m * N + gw] = acc[m] + bv;
    }
}

// ---------------- final head ----------------
__global__ void head2_kernel(const float* __restrict__ w2, const float* __restrict__ b2,
                             float* __restrict__ out) {
    int b = blockIdx.x;
    int lane = threadIdx.x;
    float acc = 0;
    for (int i = lane; i < HID; i += 32) acc += fmaxf(g_o1[(long)b * HID + i], 0.0f) * w2[i];
    #pragma unroll
    for (int o = 16; o; o >>= 1) acc += __shfl_xor_sync(~0u, acc, o);
    if (lane == 0) out[b] = acc + b2[0];
}

// ---------------- host ----------------
extern "C" void kernel_launch(void* const* d_in, const int* in_sizes, int n_in,
                              void* d_out, int out_size) {
    const float* tok_emb = (const float*)d_in[0];
    const float* pos_emb = (const float*)d_in[1];
    const float* ln1_w = (const float*)d_in[2];
    const float* ln1_b = (const float*)d_in[3];
    const float* ln2_w = (const float*)d_in[4];
    const float* ln2_b = (const float*)d_in[5];
    const float* qkv_w = (const float*)d_in[6];
    const float* out_w = (const float*)d_in[7];
    const float* route_w = (const float*)d_in[8];
    const float* route_b = (const float*)d_in[9];
    const float* noise_w = (const float*)d_in[10];
    const float* noise_b = (const float*)d_in[11];
    const float* exp_w1 = (const float*)d_in[12];
    const float* exp_b1 = (const float*)d_in[13];
    const float* exp_w2 = (const float*)d_in[14];
    const float* exp_b2 = (const float*)d_in[15];
    const float* lnf_w = (const float*)d_in[16];
    const float* lnf_b = (const float*)d_in[17];
    const float* pool_q = (const float*)d_in[18];
    const float* pool_w = (const float*)d_in[19];
    const float* pool_b = (const float*)d_in[20];
    const float* head_w1 = (const float*)d_in[21];
    const float* head_b1 = (const float*)d_in[22];
    const float* head_w2 = (const float*)d_in[23];
    const float* head_b2 = (const float*)d_in[24];
    const int* ids = (const int*)d_in[25];
    const float* rnoise = (const float*)d_in[26];
    float* out = (float*)d_out;

    float *px, *ph, *pqkv, *peout, *ppool, *phv, *po1;
    uint32_t *ppH, *ppL, *peinH, *peinL, *pehH, *pehL;
    uint32_t *pqwH, *pqwL, *powH, *powL, *pw1H, *pw1L, *pw2H, *pw2L;
    cudaGetSymbolAddress((void**)&px, g_x);
    cudaGetSymbolAddress((void**)&ph, g_h);
    cudaGetSymbolAddress((void**)&pqkv, g_qkv);
    cudaGetSymbolAddress((void**)&peout, g_eout);
    cudaGetSymbolAddress((void**)&ppool, g_pool);
    cudaGetSymbolAddress((void**)&phv, g_hv);
    cudaGetSymbolAddress((void**)&po1, g_o1);
    cudaGetSymbolAddress((void**)&ppH, g_pH);
    cudaGetSymbolAddress((void**)&ppL, g_pL);
    cudaGetSymbolAddress((void**)&peinH, g_einH);
    cudaGetSymbolAddress((void**)&peinL, g_einL);
    cudaGetSymbolAddress((void**)&pehH, g_ehH);
    cudaGetSymbolAddress((void**)&pehL, g_ehL);
    cudaGetSymbolAddress((void**)&pqwH, g_qwH);
    cudaGetSymbolAddress((void**)&pqwL, g_qwL);
    cudaGetSymbolAddress((void**)&powH, g_owH);
    cudaGetSymbolAddress((void**)&powL, g_owL);
    cudaGetSymbolAddress((void**)&pw1H, g_w1H);
    cudaGetSymbolAddress((void**)&pw1L, g_w1L);
    cudaGetSymbolAddress((void**)&pw2H, g_w2H);
    cudaGetSymbolAddress((void**)&pw2L, g_w2L);

    embed_kernel<<<NTOK, 128>>>(tok_emb, pos_emb, ids);

    for (int l = 0; l < NL; l++) {
        cvt_split<<<(3 * E * E2 + 255) / 256, 256>>>(qkv_w + (long)l * 3 * E * E, pqwH, pqwL, 3 * E * E2);
        cvt_split<<<(E * E2 + 255) / 256, 256>>>(out_w + (long)l * E * E, powH, powL, E * E2);
        cvt_split<<<(X * H4 * E2 + 255) / 256, 256>>>(exp_w1 + (long)l * X * H4 * E, pw1H, pw1L, X * H4 * E2);
        cvt_split<<<(X * E * H42 + 255) / 256, 256>>>(exp_w2 + (long)l * X * E * H4, pw2H, pw2L, X * E * H42);

        ln_kernel<<<NTOK, 256>>>(px, ln1_w + l * E, ln1_b + l * E, nullptr, ppH, ppL);
        {
            dim3 g(3 * E / 128, NTOK / 128, 1);
            gemm_bf3<<<g, 256>>>(ppH, ppL, pqwH, pqwL, nullptr, nullptr,
                                 pqkv, nullptr, nullptr, NTOK, 3 * E, E2, 0, 0, 0, 0, 0);
        }
        rope_kernel<<<NTOK, 512>>>();
        attn_tile_kernel<<<BB * HN * (T / 128), 256>>>();
        {
            dim3 g(E / 128, NTOK / 128, 1);
            gemm_bf3<<<g, 256>>>(ppH, ppL, powH, powL, nullptr, px,
                                 px, nullptr, nullptr, NTOK, E, E2, 0, 0, 0, 0, 0);
        }
        ln_kernel<<<NTOK, 256>>>(px, ln2_w + l * E, ln2_b + l * E, ph, nullptr, nullptr);
        router_kernel<<<NTOK / 8, 256>>>(route_w + (long)l * X * E, route_b + l * X,
                                         noise_w + (long)l * X * E, noise_b + l * X,
                                         rnoise + (long)l * NTOK * X);
        dispatch_kernel<<<X, 256>>>();
        gather_kernel<<<X * CAP, 128>>>();
        {
            dim3 g1(H4 / 128, CAP / 128, X);
            gemm_bf3<<<g1, 256>>>(peinH, peinL, pw1H, pw1L,
                                  exp_b1 + (long)l * X * H4, nullptr,
                                  nullptr, pehH, pehL,
                                  CAP, H4, E2, CAP * E2, H4 * E2, H4, CAP * H4, 1);
            dim3 g2(E / 128, CAP / 128, X);
            gemm_bf3<<<g2, 256>>>(pehH, pehL, pw2H, pw2L,
                                  exp_b2 + (long)l * X * E, nullptr,
                                  peout, nullptr, nullptr,
                                  CAP, E, H42, CAP * H42, E * H42, E, CAP * E, 0);
        }
        combine_kernel<<<NTOK, 128>>>();
    }

    ln_kernel<<<NTOK, 256>>>(px, lnf_w, lnf_b, ph, nullptr, nullptr);
    pool_kernel<<<BB, 256>>>(pool_q);
    gemv_mrow<<<(HIGH + 7) / 8, 256>>>(ppool, pool_w, pool_b, phv, HIGH, E);
    gemv_mrow<<<(HID + 7) / 8, 256>>>(phv, head_w1, head_b1, po1, HID, HIGH);
    head2_kernel<<<BB, 32>>>(head_w2, head_b2, out);
}